// round 9
// baseline (speedup 1.0000x reference)
#include <cuda_runtime.h>
#include <math.h>

#define N_NODES 100000
#define N_EDGES 1600000
#define NF 512
#define NH 128
#define NC 40

#define SCAN_CH  128
#define SCAN_NB  ((N_NODES + SCAN_CH - 1) / SCAN_CH)   // 782

// ---------------- scratch (static device globals; no allocation) ----------------
__device__ __align__(16) int   g_cnt   [N_NODES];
__device__ __align__(16) int   g_rowptr[N_NODES + 1];
__device__ __align__(16) int   g_cursor[N_NODES];
__device__ __align__(16) int   g_csr   [N_EDGES];
__device__ __align__(16) int   g_bsum  [SCAN_NB];
__device__ __align__(16) int   g_boff  [SCAN_NB];
__device__ __align__(16) float g_dinv  [N_NODES];
__device__ __align__(16) float g_hs1   [(size_t)N_NODES * NH];  // (x@W1) * dinv[row]
__device__ __align__(16) float g_hs2   [(size_t)N_NODES * NC];  // dinv*(z@W2)

// ---------------- helpers ----------------
__device__ __forceinline__ void mma_tf32(float* c, const unsigned int* a, const unsigned int* b) {
    asm("mma.sync.aligned.m16n8k8.row.col.f32.tf32.tf32.f32 "
        "{%0,%1,%2,%3}, {%4,%5,%6,%7}, {%8,%9}, {%0,%1,%2,%3};"
        : "+f"(c[0]), "+f"(c[1]), "+f"(c[2]), "+f"(c[3])
        : "r"(a[0]), "r"(a[1]), "r"(a[2]), "r"(a[3]), "r"(b[0]), "r"(b[1]));
}
__device__ __forceinline__ unsigned int smem_u32(const void* p) {
    return (unsigned int)__cvta_generic_to_shared(p);
}
__device__ __forceinline__ void cp16(unsigned int dst, const void* src) {
    asm volatile("cp.async.cg.shared.global [%0], [%1], 16;" :: "r"(dst), "l"(src));
}
__device__ __forceinline__ void cp16_guard(unsigned int dst, const void* src, bool valid) {
    int sz = valid ? 16 : 0;      // src-size 0 -> zero fill
    asm volatile("cp.async.cg.shared.global [%0], [%1], 16, %2;" :: "r"(dst), "l"(src), "r"(sz));
}

// ---------------- degree / dinv / CSR ----------------
__global__ void k_zero_cnt() {
    int i = blockIdx.x * blockDim.x + threadIdx.x;
    if (i < N_NODES) g_cnt[i] = 0;
}
__global__ void k_deg(const int* __restrict__ ei) {
    int e = blockIdx.x * blockDim.x + threadIdx.x;
    if (e < N_EDGES) atomicAdd(&g_cnt[ei[N_EDGES + e]], 1);
}
__global__ void k_dinv() {
    int i = blockIdx.x * blockDim.x + threadIdx.x;
    if (i < N_NODES) g_dinv[i] = rsqrtf((float)g_cnt[i] + 1.0f);  // +1 self loop
}
__global__ void __launch_bounds__(SCAN_CH) k_scan1() {
    __shared__ int wsum[4];
    const int t = threadIdx.x;
    const int i = blockIdx.x * SCAN_CH + t;
    const int lane = t & 31, warp = t >> 5;

    int v = (i < N_NODES) ? g_cnt[i] : 0;
    int s = v;
    #pragma unroll
    for (int off = 1; off < 32; off <<= 1) {
        int u = __shfl_up_sync(0xffffffffu, s, off);
        if (lane >= off) s += u;
    }
    if (lane == 31) wsum[warp] = s;
    __syncthreads();
    int wo = 0;
    #pragma unroll
    for (int w = 0; w < 4; w++) if (w < warp) wo += wsum[w];
    if (i < N_NODES) g_rowptr[i] = wo + s - v;
    if (t == SCAN_CH - 1) g_bsum[blockIdx.x] = wo + s;
}
__global__ void __launch_bounds__(1024) k_scan2() {
    __shared__ int sh[1024];
    const int t = threadIdx.x;
    int v = (t < SCAN_NB) ? g_bsum[t] : 0;
    sh[t] = v;
    __syncthreads();
    #pragma unroll
    for (int off = 1; off < 1024; off <<= 1) {
        int add = (t >= off) ? sh[t - off] : 0;
        __syncthreads();
        sh[t] += add;
        __syncthreads();
    }
    if (t < SCAN_NB) g_boff[t] = sh[t] - v;
    if (t == 0) g_rowptr[N_NODES] = sh[1023];
}
__global__ void __launch_bounds__(SCAN_CH) k_scan3() {
    const int i = blockIdx.x * SCAN_CH + threadIdx.x;
    if (i < N_NODES) {
        int r = g_rowptr[i] + g_boff[blockIdx.x];
        g_rowptr[i] = r;
        g_cursor[i] = r;
    }
}
__global__ void k_fill(const int* __restrict__ ei) {
    int e = blockIdx.x * blockDim.x + threadIdx.x;
    if (e < N_EDGES) {
        int s = ei[e], d = ei[N_EDGES + e];
        int pos = atomicAdd(&g_cursor[d], 1);
        g_csr[pos] = s;
    }
}

// ---------------- GEMM1 (tf32 MMA, cp.async double-buffered) ----------------
// raw fp32 bits fed to mma.tf32 (hw truncation; cutlass fast-tf32 path)
#define BM 128
#define BK 32
#define AS_STR 36    // floats per A row (144B, 16B-mult, conflict-free frag loads)
#define BS_STR 132   // floats per B row (528B, 16B-mult)
#define A_BUF (BM * AS_STR)          // 4608
#define B_BUF (BK * BS_STR)          // 4224
#define SMEM_UINTS (2 * (A_BUF + B_BUF))   // 17664 -> 70656 B
__global__ void __launch_bounds__(256, 2)
k_gemm1(const float* __restrict__ X, const float* __restrict__ W1) {
    extern __shared__ unsigned int smem[];
    unsigned int* A0 = smem;
    unsigned int* A1 = smem + A_BUF;
    unsigned int* B0 = smem + 2 * A_BUF;
    unsigned int* B1 = smem + 2 * A_BUF + B_BUF;

    const int tid    = threadIdx.x;
    const int lane   = tid & 31;
    const int wid    = tid >> 5;
    const int warp_m = wid >> 2;              // 0..1
    const int warp_n = wid & 3;               // 0..3
    const int block_row = blockIdx.x * BM;
    const int grp = lane >> 2;                // 0..7
    const int qid = lane & 3;                 // 0..3

    // copy slots: A row = 32 floats = 8 chunks, 2 threads/row -> 4 chunks/thread
    const int a_r  = tid >> 1;                // 0..127
    const int a_c0 = (tid & 1) * 4;           // 0 or 4
    const int b_r  = tid >> 3;                // 0..31 (8 threads per row)
    const int b_c0 = (tid & 7) * 4;           // 4 chunks spaced by 32 floats

    float acc[4][4][4];
    #pragma unroll
    for (int i = 0; i < 4; i++)
        #pragma unroll
        for (int j = 0; j < 4; j++)
            #pragma unroll
            for (int q = 0; q < 4; q++) acc[i][j][q] = 0.0f;

    const int NT = NF / BK;                   // 16 tiles

    auto prefetch = [&](int it, unsigned int* Ab, unsigned int* Bb) {
        int k0 = it * BK;
        int grow = block_row + a_r;
        bool ok = grow < N_NODES;
        const float* asrc = X + (size_t)(ok ? grow : 0) * NF + k0;
        unsigned int abase = smem_u32(Ab + a_r * AS_STR);
        #pragma unroll
        for (int ch = 0; ch < 4; ch++) {        // 4 chunks x 2 threads = 32 floats/row
            int c = a_c0 + ch * 8;              // {0,4}+{0,8,16,24} -> all 32
            cp16_guard(abase + c * 4, asrc + c, ok);
        }
        const float* bsrc = W1 + (size_t)(k0 + b_r) * NH;
        unsigned int bbase = smem_u32(Bb + b_r * BS_STR);
        #pragma unroll
        for (int ch = 0; ch < 4; ch++) {        // 4 chunks x 8 threads = 128 floats/row
            int c = b_c0 + ch * 32;
            cp16(bbase + c * 4, bsrc + c);
        }
    };

    prefetch(0, A0, B0);
    asm volatile("cp.async.commit_group;");

    #pragma unroll 1
    for (int it = 0; it < NT; it++) {
        unsigned int* Ab = (it & 1) ? A1 : A0;
        unsigned int* Bb = (it & 1) ? B1 : B0;
        if (it + 1 < NT) {
            prefetch(it + 1, (it & 1) ? A0 : A1, (it & 1) ? B0 : B1);
            asm volatile("cp.async.commit_group;");
            asm volatile("cp.async.wait_group 1;");
        } else {
            asm volatile("cp.async.wait_group 0;");
        }
        __syncthreads();

        #pragma unroll
        for (int kk = 0; kk < BK; kk += 8) {
            unsigned int af[4][4];
            #pragma unroll
            for (int mt = 0; mt < 4; mt++) {
                int r = warp_m * 64 + mt * 16;
                af[mt][0] = Ab[(r + grp    ) * AS_STR + kk + qid    ];
                af[mt][1] = Ab[(r + grp + 8) * AS_STR + kk + qid    ];
                af[mt][2] = Ab[(r + grp    ) * AS_STR + kk + qid + 4];
                af[mt][3] = Ab[(r + grp + 8) * AS_STR + kk + qid + 4];
            }
            unsigned int bf[4][2];
            #pragma unroll
            for (int nt = 0; nt < 4; nt++) {
                int c = warp_n * 32 + nt * 8 + grp;
                bf[nt][0] = Bb[(kk + qid    ) * BS_STR + c];
                bf[nt][1] = Bb[(kk + qid + 4) * BS_STR + c];
            }
            #pragma unroll
            for (int mt = 0; mt < 4; mt++)
                #pragma unroll
                for (int nt = 0; nt < 4; nt++)
                    mma_tf32(acc[mt][nt], af[mt], bf[nt]);
        }
        __syncthreads();
    }

    #pragma unroll
    for (int mt = 0; mt < 4; mt++) {
        int r1 = block_row + warp_m * 64 + mt * 16 + grp;
        int r2 = r1 + 8;
        float dv1 = (r1 < N_NODES) ? g_dinv[r1] : 0.0f;
        float dv2 = (r2 < N_NODES) ? g_dinv[r2] : 0.0f;
        #pragma unroll
        for (int nt = 0; nt < 4; nt++) {
            int col = warp_n * 32 + nt * 8 + qid * 2;
            if (r1 < N_NODES)
                *(float2*)(g_hs1 + (size_t)r1 * NH + col) =
                    make_float2(acc[mt][nt][0] * dv1, acc[mt][nt][1] * dv1);
            if (r2 < N_NODES)
                *(float2*)(g_hs1 + (size_t)r2 * NH + col) =
                    make_float2(acc[mt][nt][2] * dv2, acc[mt][nt][3] * dv2);
        }
    }
}

// ---- layer1: gather hs1 (self+neighbors), relu(dinv*agg+b1), GEMV W2 -> hs2 ----
__global__ void __launch_bounds__(256)
k_layer1(const float* __restrict__ b1, const float* __restrict__ W2) {
    __shared__ float W2s[NH * NC];    // 20 KB
    __shared__ float zs[8][NH];
    __shared__ float b1s[NH];

    const int tid  = threadIdx.x;
    const int warp = tid >> 5;
    const int lane = tid & 31;

    #pragma unroll
    for (int i = 0; i < 20; i++) {
        int idx = tid + i * 256;
        if (idx < NH * NC) W2s[idx] = W2[idx];
    }
    if (tid < NH) b1s[tid] = b1[tid];
    __syncthreads();

    #pragma unroll 1
    for (int it = 0; it < 4; it++) {
        int n = blockIdx.x * 32 + it * 8 + warp;
        float dv = g_dinv[n];

        float4 acc = *(const float4*)(g_hs1 + (size_t)n * NH + lane * 4);
        int beg = g_rowptr[n], end = g_rowptr[n + 1];
        int e = beg;
        #pragma unroll 1
        for (; e + 4 <= end; e += 4) {
            int s0 = g_csr[e], s1 = g_csr[e + 1], s2 = g_csr[e + 2], s3 = g_csr[e + 3];
            float4 v0 = *(const float4*)(g_hs1 + (size_t)s0 * NH + lane * 4);
            float4 v1 = *(const float4*)(g_hs1 + (size_t)s1 * NH + lane * 4);
            float4 v2 = *(const float4*)(g_hs1 + (size_t)s2 * NH + lane * 4);
            float4 v3 = *(const float4*)(g_hs1 + (size_t)s3 * NH + lane * 4);
            acc.x += v0.x + v1.x + v2.x + v3.x;
            acc.y += v0.y + v1.y + v2.y + v3.y;
            acc.z += v0.z + v1.z + v2.z + v3.z;
            acc.w += v0.w + v1.w + v2.w + v3.w;
        }
        #pragma unroll 1
        for (; e < end; e++) {
            int s = g_csr[e];
            float4 v = *(const float4*)(g_hs1 + (size_t)s * NH + lane * 4);
            acc.x += v.x; acc.y += v.y; acc.z += v.z; acc.w += v.w;
        }
        zs[warp][lane * 4 + 0] = fmaxf(dv * acc.x + b1s[lane * 4 + 0], 0.0f);
        zs[warp][lane * 4 + 1] = fmaxf(dv * acc.y + b1s[lane * 4 + 1], 0.0f);
        zs[warp][lane * 4 + 2] = fmaxf(dv * acc.z + b1s[lane * 4 + 2], 0.0f);
        zs[warp][lane * 4 + 3] = fmaxf(dv * acc.w + b1s[lane * 4 + 3], 0.0f);
        __syncwarp();

        float d0 = 0.0f, d1 = 0.0f;
        #pragma unroll 8
        for (int k = 0; k < NH; k++) {
            float zk = zs[warp][k];
            d0 = fmaf(zk, W2s[k * NC + lane], d0);
            if (lane < 8) d1 = fmaf(zk, W2s[k * NC + 32 + lane], d1);
        }
        g_hs2[(size_t)n * NC + lane] = dv * d0;
        if (lane < 8) g_hs2[(size_t)n * NC + 32 + lane] = dv * d1;
        __syncwarp();
    }
}

// ---- layer2: gather hs2 (self+neighbors), bias + log_softmax -> out ----
__global__ void __launch_bounds__(256)
k_layer2(const float* __restrict__ b2, float* __restrict__ out) {
    int n    = blockIdx.x * 8 + (threadIdx.x >> 5);
    int lane = threadIdx.x & 31;
    float dv = g_dinv[n];
    size_t base = (size_t)n * NC;

    float v0 = g_hs2[base + lane];
    float v1 = (lane < 8) ? g_hs2[base + 32 + lane] : 0.0f;

    int beg = g_rowptr[n], end = g_rowptr[n + 1];
    int e = beg;
    #pragma unroll 1
    for (; e + 2 <= end; e += 2) {
        int s0 = g_csr[e], s1 = g_csr[e + 1];
        size_t sb0 = (size_t)s0 * NC, sb1 = (size_t)s1 * NC;
        float a0 = g_hs2[sb0 + lane], a1 = g_hs2[sb1 + lane];
        v0 += a0 + a1;
        if (lane < 8) v1 += g_hs2[sb0 + 32 + lane] + g_hs2[sb1 + 32 + lane];
    }
    if (e < end) {
        size_t sb = (size_t)g_csr[e] * NC;
        v0 += g_hs2[sb + lane];
        if (lane < 8) v1 += g_hs2[sb + 32 + lane];
    }

    v0 = dv * v0 + b2[lane];
    v1 = (lane < 8) ? (dv * v1 + b2[32 + lane]) : -3.0e38f;

    float m = fmaxf(v0, v1);
    #pragma unroll
    for (int off = 16; off; off >>= 1)
        m = fmaxf(m, __shfl_xor_sync(0xffffffffu, m, off));

    float ssum = expf(v0 - m) + ((lane < 8) ? expf(v1 - m) : 0.0f);
    #pragma unroll
    for (int off = 16; off; off >>= 1)
        ssum += __shfl_xor_sync(0xffffffffu, ssum, off);

    float lse = m + logf(ssum);
    out[base + lane] = v0 - lse;
    if (lane < 8) out[base + 32 + lane] = v1 - lse;
}

// ---------------- launch ----------------
extern "C" void kernel_launch(void* const* d_in, const int* in_sizes, int n_in,
                              void* d_out, int out_size) {
    const float* x = 0; const int* ei = 0;
    const float* W1 = 0; const float* b1 = 0;
    const float* W2 = 0; const float* b2 = 0;
    for (int i = 0; i < n_in; i++) {
        switch (in_sizes[i]) {
            case 51200000: x  = (const float*)d_in[i]; break;
            case 3200000:  ei = (const int*)d_in[i];   break;
            case 65536:    W1 = (const float*)d_in[i]; break;
            case 128:      b1 = (const float*)d_in[i]; break;
            case 5120:     W2 = (const float*)d_in[i]; break;
            case 40:       b2 = (const float*)d_in[i]; break;
        }
    }
    float* out = (float*)d_out;

    cudaFuncSetAttribute(k_gemm1, cudaFuncAttributeMaxDynamicSharedMemorySize,
                         SMEM_UINTS * 4);

    k_zero_cnt<<<(N_NODES + 255) / 256, 256>>>();
    k_deg<<<(N_EDGES + 255) / 256, 256>>>(ei);
    k_dinv<<<(N_NODES + 255) / 256, 256>>>();
    k_scan1<<<SCAN_NB, SCAN_CH>>>();
    k_scan2<<<1, 1024>>>();
    k_scan3<<<SCAN_NB, SCAN_CH>>>();
    k_fill<<<(N_EDGES + 255) / 256, 256>>>(ei);

    k_gemm1<<<(N_NODES + BM - 1) / BM, 256, SMEM_UINTS * 4>>>(x, W1);
    k_layer1<<<N_NODES / 32, 256>>>(b1, W2);
    k_layer2<<<N_NODES / 8, 256>>>(b2, out);
}

// round 11
// speedup vs baseline: 1.0333x; 1.0333x over previous
#include <cuda_runtime.h>
#include <math.h>

#define N_NODES 100000
#define N_EDGES 1600000
#define NF 512
#define NH 128
#define NC 40
#define NHW (NH / 2)   // 64 bf16x2 words per hs1 row
#define NCW (NC / 2)   // 20 bf16x2 words per hs2 row

#define SCAN_CH  128
#define SCAN_NB  ((N_NODES + SCAN_CH - 1) / SCAN_CH)   // 782

// ---------------- scratch (static device globals; no allocation) ----------------
__device__ __align__(16) int          g_cnt   [N_NODES];
__device__ __align__(16) int          g_rowptr[N_NODES + 1];
__device__ __align__(16) int          g_cursor[N_NODES];
__device__ __align__(16) int          g_csr   [N_EDGES];
__device__ __align__(16) int          g_bsum  [SCAN_NB];
__device__ __align__(16) int          g_boff  [SCAN_NB];
__device__ __align__(16) float        g_dinv  [N_NODES];
__device__ __align__(16) unsigned int g_hs1b  [(size_t)N_NODES * NHW]; // bf16x2
__device__ __align__(16) unsigned int g_hs2b  [(size_t)N_NODES * NCW]; // bf16x2

// ---------------- helpers ----------------
__device__ __forceinline__ void mma_tf32(float* c, const unsigned int* a, const unsigned int* b) {
    asm("mma.sync.aligned.m16n8k8.row.col.f32.tf32.tf32.f32 "
        "{%0,%1,%2,%3}, {%4,%5,%6,%7}, {%8,%9}, {%0,%1,%2,%3};"
        : "+f"(c[0]), "+f"(c[1]), "+f"(c[2]), "+f"(c[3])
        : "r"(a[0]), "r"(a[1]), "r"(a[2]), "r"(a[3]), "r"(b[0]), "r"(b[1]));
}
__device__ __forceinline__ unsigned int smem_u32(const void* p) {
    return (unsigned int)__cvta_generic_to_shared(p);
}
__device__ __forceinline__ void cp16(unsigned int dst, const void* src) {
    asm volatile("cp.async.cg.shared.global [%0], [%1], 16;" :: "r"(dst), "l"(src));
}
__device__ __forceinline__ void cp16_guard(unsigned int dst, const void* src, bool valid) {
    int sz = valid ? 16 : 0;
    asm volatile("cp.async.cg.shared.global [%0], [%1], 16, %2;" :: "r"(dst), "l"(src), "r"(sz));
}
__device__ __forceinline__ unsigned int pack_bf16x2(float lo, float hi) {
    unsigned int r;
    asm("cvt.rn.bf16x2.f32 %0, %1, %2;" : "=r"(r) : "f"(hi), "f"(lo));
    return r;
}
__device__ __forceinline__ float bf_lo(unsigned int w) { return __uint_as_float(w << 16); }
__device__ __forceinline__ float bf_hi(unsigned int w) { return __uint_as_float(w & 0xffff0000u); }

// ---------------- degree / dinv / CSR ----------------
__global__ void k_zero_cnt() {
    int i = blockIdx.x * blockDim.x + threadIdx.x;
    if (i < N_NODES) g_cnt[i] = 0;
}
__global__ void k_deg(const int* __restrict__ ei) {
    int e = blockIdx.x * blockDim.x + threadIdx.x;
    if (e < N_EDGES) atomicAdd(&g_cnt[ei[N_EDGES + e]], 1);
}
__global__ void k_dinv() {
    int i = blockIdx.x * blockDim.x + threadIdx.x;
    if (i < N_NODES) g_dinv[i] = rsqrtf((float)g_cnt[i] + 1.0f);  // +1 self loop
}
__global__ void __launch_bounds__(SCAN_CH) k_scan1() {
    __shared__ int wsum[4];
    const int t = threadIdx.x;
    const int i = blockIdx.x * SCAN_CH + t;
    const int lane = t & 31, warp = t >> 5;

    int v = (i < N_NODES) ? g_cnt[i] : 0;
    int s = v;
    #pragma unroll
    for (int off = 1; off < 32; off <<= 1) {
        int u = __shfl_up_sync(0xffffffffu, s, off);
        if (lane >= off) s += u;
    }
    if (lane == 31) wsum[warp] = s;
    __syncthreads();
    int wo = 0;
    #pragma unroll
    for (int w = 0; w < 4; w++) if (w < warp) wo += wsum[w];
    if (i < N_NODES) g_rowptr[i] = wo + s - v;
    if (t == SCAN_CH - 1) g_bsum[blockIdx.x] = wo + s;
}
__global__ void __launch_bounds__(1024) k_scan2() {
    __shared__ int sh[1024];
    const int t = threadIdx.x;
    int v = (t < SCAN_NB) ? g_bsum[t] : 0;
    sh[t] = v;
    __syncthreads();
    #pragma unroll
    for (int off = 1; off < 1024; off <<= 1) {
        int add = (t >= off) ? sh[t - off] : 0;
        __syncthreads();
        sh[t] += add;
        __syncthreads();
    }
    if (t < SCAN_NB) g_boff[t] = sh[t] - v;
    if (t == 0) g_rowptr[N_NODES] = sh[1023];
}
__global__ void __launch_bounds__(SCAN_CH) k_scan3() {
    const int i = blockIdx.x * SCAN_CH + threadIdx.x;
    if (i < N_NODES) {
        int r = g_rowptr[i] + g_boff[blockIdx.x];
        g_rowptr[i] = r;
        g_cursor[i] = r;
    }
}
__global__ void k_fill(const int* __restrict__ ei) {
    int e = blockIdx.x * blockDim.x + threadIdx.x;
    if (e < N_EDGES) {
        int s = ei[e], d = ei[N_EDGES + e];
        int pos = atomicAdd(&g_cursor[d], 1);
        g_csr[pos] = s;
    }
}

// ---------------- GEMM1 (tf32 MMA, cp.async double-buffered) ----------------
#define BM 128
#define BK 32
#define AS_STR 36
#define BS_STR 132
#define A_BUF (BM * AS_STR)
#define B_BUF (BK * BS_STR)
#define SMEM_UINTS (2 * (A_BUF + B_BUF))
__global__ void __launch_bounds__(256, 2)
k_gemm1(const float* __restrict__ X, const float* __restrict__ W1) {
    extern __shared__ unsigned int smem[];
    unsigned int* A0 = smem;
    unsigned int* A1 = smem + A_BUF;
    unsigned int* B0 = smem + 2 * A_BUF;
    unsigned int* B1 = smem + 2 * A_BUF + B_BUF;

    const int tid    = threadIdx.x;
    const int lane   = tid & 31;
    const int wid    = tid >> 5;
    const int warp_m = wid >> 2;
    const int warp_n = wid & 3;
    const int block_row = blockIdx.x * BM;
    const int grp = lane >> 2;
    const int qid = lane & 3;

    const int a_r  = tid >> 1;
    const int a_c0 = (tid & 1) * 4;
    const int b_r  = tid >> 3;
    const int b_c0 = (tid & 7) * 4;

    float acc[4][4][4];
    #pragma unroll
    for (int i = 0; i < 4; i++)
        #pragma unroll
        for (int j = 0; j < 4; j++)
            #pragma unroll
            for (int q = 0; q < 4; q++) acc[i][j][q] = 0.0f;

    const int NT = NF / BK;

    auto prefetch = [&](int it, unsigned int* Ab, unsigned int* Bb) {
        int k0 = it * BK;
        int grow = block_row + a_r;
        bool ok = grow < N_NODES;
        const float* asrc = X + (size_t)(ok ? grow : 0) * NF + k0;
        unsigned int abase = smem_u32(Ab + a_r * AS_STR);
        #pragma unroll
        for (int ch = 0; ch < 4; ch++) {
            int c = a_c0 + ch * 8;
            cp16_guard(abase + c * 4, asrc + c, ok);
        }
        const float* bsrc = W1 + (size_t)(k0 + b_r) * NH;
        unsigned int bbase = smem_u32(Bb + b_r * BS_STR);
        #pragma unroll
        for (int ch = 0; ch < 4; ch++) {
            int c = b_c0 + ch * 32;
            cp16(bbase + c * 4, bsrc + c);
        }
    };

    prefetch(0, A0, B0);
    asm volatile("cp.async.commit_group;");

    #pragma unroll 1
    for (int it = 0; it < NT; it++) {
        unsigned int* Ab = (it & 1) ? A1 : A0;
        unsigned int* Bb = (it & 1) ? B1 : B0;
        if (it + 1 < NT) {
            prefetch(it + 1, (it & 1) ? A0 : A1, (it & 1) ? B0 : B1);
            asm volatile("cp.async.commit_group;");
            asm volatile("cp.async.wait_group 1;");
        } else {
            asm volatile("cp.async.wait_group 0;");
        }
        __syncthreads();

        #pragma unroll
        for (int kk = 0; kk < BK; kk += 8) {
            unsigned int af[4][4];
            #pragma unroll
            for (int mt = 0; mt < 4; mt++) {
                int r = warp_m * 64 + mt * 16;
                af[mt][0] = Ab[(r + grp    ) * AS_STR + kk + qid    ];
                af[mt][1] = Ab[(r + grp + 8) * AS_STR + kk + qid    ];
                af[mt][2] = Ab[(r + grp    ) * AS_STR + kk + qid + 4];
                af[mt][3] = Ab[(r + grp + 8) * AS_STR + kk + qid + 4];
            }
            unsigned int bf[4][2];
            #pragma unroll
            for (int nt = 0; nt < 4; nt++) {
                int c = warp_n * 32 + nt * 8 + grp;
                bf[nt][0] = Bb[(kk + qid    ) * BS_STR + c];
                bf[nt][1] = Bb[(kk + qid + 4) * BS_STR + c];
            }
            #pragma unroll
            for (int mt = 0; mt < 4; mt++)
                #pragma unroll
                for (int nt = 0; nt < 4; nt++)
                    mma_tf32(acc[mt][nt], af[mt], bf[nt]);
        }
        __syncthreads();
    }

    // epilogue: scale by dinv, pack bf16x2, write hs1b
    #pragma unroll
    for (int mt = 0; mt < 4; mt++) {
        int r1 = block_row + warp_m * 64 + mt * 16 + grp;
        int r2 = r1 + 8;
        float dv1 = (r1 < N_NODES) ? g_dinv[r1] : 0.0f;
        float dv2 = (r2 < N_NODES) ? g_dinv[r2] : 0.0f;
        #pragma unroll
        for (int nt = 0; nt < 4; nt++) {
            int col = warp_n * 32 + nt * 8 + qid * 2;   // even
            if (r1 < N_NODES)
                g_hs1b[(size_t)r1 * NHW + (col >> 1)] =
                    pack_bf16x2(acc[mt][nt][0] * dv1, acc[mt][nt][1] * dv1);
            if (r2 < N_NODES)
                g_hs1b[(size_t)r2 * NHW + (col >> 1)] =
                    pack_bf16x2(acc[mt][nt][2] * dv2, acc[mt][nt][3] * dv2);
        }
    }
}

// ---- layer1: gather bf16 hs1 (self+neighbors), relu(dinv*agg+b1), GEMV W2 ----
__global__ void __launch_bounds__(256)
k_layer1(const float* __restrict__ b1, const float* __restrict__ W2) {
    __shared__ float W2s[NH * NC];    // 20 KB
    __shared__ float zs[8][NH];
    __shared__ float hrow[8][NC];
    __shared__ float b1s[NH];

    const int tid  = threadIdx.x;
    const int warp = tid >> 5;
    const int lane = tid & 31;

    #pragma unroll
    for (int i = 0; i < 20; i++) {
        int idx = tid + i * 256;
        if (idx < NH * NC) W2s[idx] = W2[idx];
    }
    if (tid < NH) b1s[tid] = b1[tid];
    __syncthreads();

    #pragma unroll 1
    for (int it = 0; it < 4; it++) {
        int n = blockIdx.x * 32 + it * 8 + warp;
        float dv = g_dinv[n];

        // each lane owns words 2*lane, 2*lane+1  (feats 4l..4l+3)
        const unsigned int* selfp = g_hs1b + (size_t)n * NHW + lane * 2;
        uint2 sw = *(const uint2*)selfp;
        float a0 = bf_lo(sw.x), a1 = bf_hi(sw.x), a2 = bf_lo(sw.y), a3 = bf_hi(sw.y);

        int beg = g_rowptr[n], end = g_rowptr[n + 1];
        int e = beg;
        #pragma unroll 1
        for (; e + 4 <= end; e += 4) {
            int s0 = g_csr[e], s1 = g_csr[e + 1], s2 = g_csr[e + 2], s3 = g_csr[e + 3];
            uint2 w0 = *(const uint2*)(g_hs1b + (size_t)s0 * NHW + lane * 2);
            uint2 w1 = *(const uint2*)(g_hs1b + (size_t)s1 * NHW + lane * 2);
            uint2 w2 = *(const uint2*)(g_hs1b + (size_t)s2 * NHW + lane * 2);
            uint2 w3 = *(const uint2*)(g_hs1b + (size_t)s3 * NHW + lane * 2);
            a0 += bf_lo(w0.x) + bf_lo(w1.x) + bf_lo(w2.x) + bf_lo(w3.x);
            a1 += bf_hi(w0.x) + bf_hi(w1.x) + bf_hi(w2.x) + bf_hi(w3.x);
            a2 += bf_lo(w0.y) + bf_lo(w1.y) + bf_lo(w2.y) + bf_lo(w3.y);
            a3 += bf_hi(w0.y) + bf_hi(w1.y) + bf_hi(w2.y) + bf_hi(w3.y);
        }
        #pragma unroll 1
        for (; e < end; e++) {
            int s = g_csr[e];
            uint2 w = *(const uint2*)(g_hs1b + (size_t)s * NHW + lane * 2);
            a0 += bf_lo(w.x); a1 += bf_hi(w.x); a2 += bf_lo(w.y); a3 += bf_hi(w.y);
        }
        zs[warp][lane * 4 + 0] = fmaxf(dv * a0 + b1s[lane * 4 + 0], 0.0f);
        zs[warp][lane * 4 + 1] = fmaxf(dv * a1 + b1s[lane * 4 + 1], 0.0f);
        zs[warp][lane * 4 + 2] = fmaxf(dv * a2 + b1s[lane * 4 + 2], 0.0f);
        zs[warp][lane * 4 + 3] = fmaxf(dv * a3 + b1s[lane * 4 + 3], 0.0f);
        __syncwarp();

        float d0 = 0.0f, d1 = 0.0f;
        #pragma unroll 8
        for (int k = 0; k < NH; k++) {
            float zk = zs[warp][k];
            d0 = fmaf(zk, W2s[k * NC + lane], d0);
            if (lane < 8) d1 = fmaf(zk, W2s[k * NC + 32 + lane], d1);
        }
        hrow[warp][lane < NC ? lane : 0] = (lane < NC) ? dv * d0 : hrow[warp][0];
        hrow[warp][lane] = dv * d0;               // lanes 0..31 (only 0..39 used)
        if (lane < 8) hrow[warp][32 + lane] = dv * d1;
        __syncwarp();
        if (lane < NCW)
            g_hs2b[(size_t)n * NCW + lane] =
                pack_bf16x2(hrow[warp][lane * 2], hrow[warp][lane * 2 + 1]);
        __syncwarp();
    }
}

// ---- layer2: gather bf16 hs2 (self+neighbors), bias + log_softmax -> out ----
__global__ void __launch_bounds__(256)
k_layer2(const float* __restrict__ b2, float* __restrict__ out) {
    int n    = blockIdx.x * 8 + (threadIdx.x >> 5);
    int lane = threadIdx.x & 31;
    float dv = g_dinv[n];
    const bool act = lane < NCW;                 // lanes 0..19 own elems 2l, 2l+1
    size_t baseb = (size_t)n * NCW;

    float v0 = 0.0f, v1 = 0.0f;
    if (act) {
        unsigned int w = g_hs2b[baseb + lane];
        v0 = bf_lo(w); v1 = bf_hi(w);
    }
    int beg = g_rowptr[n], end = g_rowptr[n + 1];
    int e = beg;
    #pragma unroll 1
    for (; e + 2 <= end; e += 2) {
        int s0 = g_csr[e], s1 = g_csr[e + 1];
        if (act) {
            unsigned int w0 = g_hs2b[(size_t)s0 * NCW + lane];
            unsigned int w1 = g_hs2b[(size_t)s1 * NCW + lane];
            v0 += bf_lo(w0) + bf_lo(w1);
            v1 += bf_hi(w0) + bf_hi(w1);
        }
    }
    if (e < end) {
        if (act) {
            unsigned int w = g_hs2b[(size_t)g_csr[e] * NCW + lane];
            v0 += bf_lo(w); v1 += bf_hi(w);
        }
    }

    if (act) {
        v0 = dv * v0 + b2[lane * 2];
        v1 = dv * v1 + b2[lane * 2 + 1];
    } else {
        v0 = -3.0e38f; v1 = -3.0e38f;
    }

    float m = fmaxf(v0, v1);
    #pragma unroll
    for (int off = 16; off; off >>= 1)
        m = fmaxf(m, __shfl_xor_sync(0xffffffffu, m, off));

    float ssum = act ? (expf(v0 - m) + expf(v1 - m)) : 0.0f;
    #pragma unroll
    for (int off = 16; off; off >>= 1)
        ssum += __shfl_xor_sync(0xffffffffu, ssum, off);

    float lse = m + logf(ssum);
    if (act)
        *(float2*)(out + (size_t)n * NC + lane * 2) = make_float2(v0 - lse, v1 - lse);
}

// ---------------- launch ----------------
extern "C" void kernel_launch(void* const* d_in, const int* in_sizes, int n_in,
                              void* d_out, int out_size) {
    const float* x = 0; const int* ei = 0;
    const float* W1 = 0; const float* b1 = 0;
    const float* W2 = 0; const float* b2 = 0;
    for (int i = 0; i < n_in; i++) {
        switch (in_sizes[i]) {
            case 51200000: x  = (const float*)d_in[i]; break;
            case 3200000:  ei = (const int*)d_in[i];   break;
            case 65536:    W1 = (const float*)d_in[i]; break;
            case 128:      b1 = (const float*)d_in[i]; break;
            case 5120:     W2 = (const float*)d_in[i]; break;
            case 40:       b2 = (const float*)d_in[i]; break;
        }
    }
    float* out = (float*)d_out;

    cudaFuncSetAttribute(k_gemm1, cudaFuncAttributeMaxDynamicSharedMemorySize,
                         SMEM_UINTS * 4);

    k_zero_cnt<<<(N_NODES + 255) / 256, 256>>>();
    k_deg<<<(N_EDGES + 255) / 256, 256>>>(ei);
    k_dinv<<<(N_NODES + 255) / 256, 256>>>();
    // gemm1 as 4th launch: only needs dinv, and it lands in the profiler slot
    k_gemm1<<<(N_NODES + BM - 1) / BM, 256, SMEM_UINTS * 4>>>(x, W1);
    k_scan1<<<SCAN_NB, SCAN_CH>>>();
    k_scan2<<<1, 1024>>>();
    k_scan3<<<SCAN_NB, SCAN_CH>>>();
    k_fill<<<(N_EDGES + 255) / 256, 256>>>(ei);

    k_layer1<<<N_NODES / 32, 256>>>(b1, W2);
    k_layer2<<<N_NODES / 8, 256>>>(b2, out);
}

// round 12
// speedup vs baseline: 1.2848x; 1.2434x over previous
#include <cuda_runtime.h>
#include <math.h>

#define N_NODES 100000
#define N_EDGES 1600000
#define NF 512
#define NH 128
#define NC 40
#define NHW (NH / 2)   // 64 bf16x2 words per hs1 row
#define NCW (NC / 2)   // 20 bf16x2 words per hs2 row

#define SCAN_CH  128
#define SCAN_NB  ((N_NODES + SCAN_CH - 1) / SCAN_CH)   // 782

// ---------------- scratch (static device globals; no allocation) ----------------
__device__ __align__(16) int          g_cnt   [N_NODES];
__device__ __align__(16) int          g_rowptr[N_NODES + 1];
__device__ __align__(16) int          g_cursor[N_NODES];
__device__ __align__(16) int          g_csr   [N_EDGES];
__device__ __align__(16) int          g_bsum  [SCAN_NB];
__device__ __align__(16) int          g_boff  [SCAN_NB];
__device__ __align__(16) float        g_dinv  [N_NODES];
__device__ __align__(16) unsigned int g_hs1b  [(size_t)N_NODES * NHW]; // bf16x2
__device__ __align__(16) unsigned int g_hs2b  [(size_t)N_NODES * NCW]; // bf16x2

// ---------------- helpers ----------------
__device__ __forceinline__ void mma_tf32(float* c, const unsigned int* a, const unsigned int* b) {
    asm("mma.sync.aligned.m16n8k8.row.col.f32.tf32.tf32.f32 "
        "{%0,%1,%2,%3}, {%4,%5,%6,%7}, {%8,%9}, {%0,%1,%2,%3};"
        : "+f"(c[0]), "+f"(c[1]), "+f"(c[2]), "+f"(c[3])
        : "r"(a[0]), "r"(a[1]), "r"(a[2]), "r"(a[3]), "r"(b[0]), "r"(b[1]));
}
__device__ __forceinline__ void mma_bf16(float* c, unsigned int a0, unsigned int a1,
                                         unsigned int a2, unsigned int a3,
                                         unsigned int b0, unsigned int b1) {
    asm("mma.sync.aligned.m16n8k16.row.col.f32.bf16.bf16.f32 "
        "{%0,%1,%2,%3}, {%4,%5,%6,%7}, {%8,%9}, {%0,%1,%2,%3};"
        : "+f"(c[0]), "+f"(c[1]), "+f"(c[2]), "+f"(c[3])
        : "r"(a0), "r"(a1), "r"(a2), "r"(a3), "r"(b0), "r"(b1));
}
__device__ __forceinline__ unsigned int smem_u32(const void* p) {
    return (unsigned int)__cvta_generic_to_shared(p);
}
__device__ __forceinline__ void cp16(unsigned int dst, const void* src) {
    asm volatile("cp.async.cg.shared.global [%0], [%1], 16;" :: "r"(dst), "l"(src));
}
__device__ __forceinline__ void cp16_guard(unsigned int dst, const void* src, bool valid) {
    int sz = valid ? 16 : 0;
    asm volatile("cp.async.cg.shared.global [%0], [%1], 16, %2;" :: "r"(dst), "l"(src), "r"(sz));
}
__device__ __forceinline__ unsigned int pack_bf16x2(float lo, float hi) {
    unsigned int r;
    asm("cvt.rn.bf16x2.f32 %0, %1, %2;" : "=r"(r) : "f"(hi), "f"(lo));
    return r;
}
__device__ __forceinline__ float bf_lo(unsigned int w) { return __uint_as_float(w << 16); }
__device__ __forceinline__ float bf_hi(unsigned int w) { return __uint_as_float(w & 0xffff0000u); }

// ---------------- degree / dinv / CSR ----------------
__global__ void k_zero_cnt() {
    int i = blockIdx.x * blockDim.x + threadIdx.x;
    if (i < N_NODES) g_cnt[i] = 0;
}
__global__ void k_deg(const int* __restrict__ ei) {
    int e = blockIdx.x * blockDim.x + threadIdx.x;
    if (e < N_EDGES) atomicAdd(&g_cnt[ei[N_EDGES + e]], 1);
}
// scan phase 1 + dinv (reads g_cnt anyway)
__global__ void __launch_bounds__(SCAN_CH) k_scan1() {
    __shared__ int wsum[4];
    const int t = threadIdx.x;
    const int i = blockIdx.x * SCAN_CH + t;
    const int lane = t & 31, warp = t >> 5;

    int v = (i < N_NODES) ? g_cnt[i] : 0;
    if (i < N_NODES) g_dinv[i] = rsqrtf((float)v + 1.0f);   // +1 self loop
    int s = v;
    #pragma unroll
    for (int off = 1; off < 32; off <<= 1) {
        int u = __shfl_up_sync(0xffffffffu, s, off);
        if (lane >= off) s += u;
    }
    if (lane == 31) wsum[warp] = s;
    __syncthreads();
    int wo = 0;
    #pragma unroll
    for (int w = 0; w < 4; w++) if (w < warp) wo += wsum[w];
    if (i < N_NODES) g_rowptr[i] = wo + s - v;
    if (t == SCAN_CH - 1) g_bsum[blockIdx.x] = wo + s;
}
__global__ void __launch_bounds__(1024) k_scan2() {
    __shared__ int sh[1024];
    const int t = threadIdx.x;
    int v = (t < SCAN_NB) ? g_bsum[t] : 0;
    sh[t] = v;
    __syncthreads();
    #pragma unroll
    for (int off = 1; off < 1024; off <<= 1) {
        int add = (t >= off) ? sh[t - off] : 0;
        __syncthreads();
        sh[t] += add;
        __syncthreads();
    }
    if (t < SCAN_NB) g_boff[t] = sh[t] - v;
    if (t == 0) g_rowptr[N_NODES] = sh[1023];
}
__global__ void __launch_bounds__(SCAN_CH) k_scan3() {
    const int i = blockIdx.x * SCAN_CH + threadIdx.x;
    if (i < N_NODES) {
        int r = g_rowptr[i] + g_boff[blockIdx.x];
        g_rowptr[i] = r;
        g_cursor[i] = r;
    }
}
__global__ void k_fill(const int* __restrict__ ei) {
    int e = blockIdx.x * blockDim.x + threadIdx.x;
    if (e < N_EDGES) {
        int s = ei[e], d = ei[N_EDGES + e];
        int pos = atomicAdd(&g_cursor[d], 1);
        g_csr[pos] = s;
    }
}

// ---------------- GEMM1 (tf32 MMA, cp.async double-buffered) ----------------
#define BM 128
#define BK 32
#define AS_STR 36
#define BS_STR 132
#define A_BUF (BM * AS_STR)
#define B_BUF (BK * BS_STR)
#define SMEM_UINTS (2 * (A_BUF + B_BUF))
__global__ void __launch_bounds__(256, 2)
k_gemm1(const float* __restrict__ X, const float* __restrict__ W1) {
    extern __shared__ unsigned int smem[];
    unsigned int* A0 = smem;
    unsigned int* A1 = smem + A_BUF;
    unsigned int* B0 = smem + 2 * A_BUF;
    unsigned int* B1 = smem + 2 * A_BUF + B_BUF;

    const int tid    = threadIdx.x;
    const int lane   = tid & 31;
    const int wid    = tid >> 5;
    const int warp_m = wid >> 2;
    const int warp_n = wid & 3;
    const int block_row = blockIdx.x * BM;
    const int grp = lane >> 2;
    const int qid = lane & 3;

    const int a_r  = tid >> 1;
    const int a_c0 = (tid & 1) * 4;
    const int b_r  = tid >> 3;
    const int b_c0 = (tid & 7) * 4;

    float acc[4][4][4];
    #pragma unroll
    for (int i = 0; i < 4; i++)
        #pragma unroll
        for (int j = 0; j < 4; j++)
            #pragma unroll
            for (int q = 0; q < 4; q++) acc[i][j][q] = 0.0f;

    const int NT = NF / BK;

    auto prefetch = [&](int it, unsigned int* Ab, unsigned int* Bb) {
        int k0 = it * BK;
        int grow = block_row + a_r;
        bool ok = grow < N_NODES;
        const float* asrc = X + (size_t)(ok ? grow : 0) * NF + k0;
        unsigned int abase = smem_u32(Ab + a_r * AS_STR);
        #pragma unroll
        for (int ch = 0; ch < 4; ch++) {
            int c = a_c0 + ch * 8;
            cp16_guard(abase + c * 4, asrc + c, ok);
        }
        const float* bsrc = W1 + (size_t)(k0 + b_r) * NH;
        unsigned int bbase = smem_u32(Bb + b_r * BS_STR);
        #pragma unroll
        for (int ch = 0; ch < 4; ch++) {
            int c = b_c0 + ch * 32;
            cp16(bbase + c * 4, bsrc + c);
        }
    };

    prefetch(0, A0, B0);
    asm volatile("cp.async.commit_group;");

    #pragma unroll 1
    for (int it = 0; it < NT; it++) {
        unsigned int* Ab = (it & 1) ? A1 : A0;
        unsigned int* Bb = (it & 1) ? B1 : B0;
        if (it + 1 < NT) {
            prefetch(it + 1, (it & 1) ? A0 : A1, (it & 1) ? B0 : B1);
            asm volatile("cp.async.commit_group;");
            asm volatile("cp.async.wait_group 1;");
        } else {
            asm volatile("cp.async.wait_group 0;");
        }
        __syncthreads();

        #pragma unroll
        for (int kk = 0; kk < BK; kk += 8) {
            unsigned int af[4][4];
            #pragma unroll
            for (int mt = 0; mt < 4; mt++) {
                int r = warp_m * 64 + mt * 16;
                af[mt][0] = Ab[(r + grp    ) * AS_STR + kk + qid    ];
                af[mt][1] = Ab[(r + grp + 8) * AS_STR + kk + qid    ];
                af[mt][2] = Ab[(r + grp    ) * AS_STR + kk + qid + 4];
                af[mt][3] = Ab[(r + grp + 8) * AS_STR + kk + qid + 4];
            }
            unsigned int bf[4][2];
            #pragma unroll
            for (int nt = 0; nt < 4; nt++) {
                int c = warp_n * 32 + nt * 8 + grp;
                bf[nt][0] = Bb[(kk + qid    ) * BS_STR + c];
                bf[nt][1] = Bb[(kk + qid + 4) * BS_STR + c];
            }
            #pragma unroll
            for (int mt = 0; mt < 4; mt++)
                #pragma unroll
                for (int nt = 0; nt < 4; nt++)
                    mma_tf32(acc[mt][nt], af[mt], bf[nt]);
        }
        __syncthreads();
    }

    #pragma unroll
    for (int mt = 0; mt < 4; mt++) {
        int r1 = block_row + warp_m * 64 + mt * 16 + grp;
        int r2 = r1 + 8;
        float dv1 = (r1 < N_NODES) ? g_dinv[r1] : 0.0f;
        float dv2 = (r2 < N_NODES) ? g_dinv[r2] : 0.0f;
        #pragma unroll
        for (int nt = 0; nt < 4; nt++) {
            int col = warp_n * 32 + nt * 8 + qid * 2;
            if (r1 < N_NODES)
                g_hs1b[(size_t)r1 * NHW + (col >> 1)] =
                    pack_bf16x2(acc[mt][nt][0] * dv1, acc[mt][nt][1] * dv1);
            if (r2 < N_NODES)
                g_hs1b[(size_t)r2 * NHW + (col >> 1)] =
                    pack_bf16x2(acc[mt][nt][2] * dv2, acc[mt][nt][3] * dv2);
        }
    }
}

// ---- layer1: gather bf16 hs1 -> z (smem, bf16), then block MMA z@W2 -> hs2b ----
#define Z_STRW 68   // u32 words per z row (64 used + 4 pad) -> 272B stride
__global__ void __launch_bounds__(256)
k_layer1(const float* __restrict__ b1, const float* __restrict__ W2) {
    __shared__ unsigned int zsb[32][Z_STRW];   // z rows, bf16x2
    __shared__ unsigned int W2T[NC][Z_STRW];   // W2^T rows (n-major), bf16x2
    __shared__ float b1s[NH];
    __shared__ float dvs[32];

    const int tid  = threadIdx.x;
    const int warp = tid >> 5;
    const int lane = tid & 31;
    const int grp  = lane >> 2;
    const int qid  = lane & 3;

    // W2T[n][w] packs W2[2w][n], W2[2w+1][n]
    #pragma unroll
    for (int i = tid; i < NC * 64; i += 256) {
        int n = i >> 6, w = i & 63;
        W2T[n][w] = pack_bf16x2(W2[(2 * w) * NC + n], W2[(2 * w + 1) * NC + n]);
    }
    if (tid < NH) b1s[tid] = b1[tid];
    __syncthreads();

    // phase A: gather + relu -> zsb (warp per node, 4 nodes per warp)
    #pragma unroll 1
    for (int it = 0; it < 4; it++) {
        int nl = it * 8 + warp;                  // local node 0..31
        int n  = blockIdx.x * 32 + nl;
        float dv = g_dinv[n];
        if (lane == 0) dvs[nl] = dv;

        uint2 sw = *(const uint2*)(g_hs1b + (size_t)n * NHW + lane * 2);
        float a0 = bf_lo(sw.x), a1 = bf_hi(sw.x), a2 = bf_lo(sw.y), a3 = bf_hi(sw.y);

        int beg = g_rowptr[n], end = g_rowptr[n + 1];
        int e = beg;
        #pragma unroll 1
        for (; e + 4 <= end; e += 4) {
            int s0 = g_csr[e], s1 = g_csr[e + 1], s2 = g_csr[e + 2], s3 = g_csr[e + 3];
            uint2 w0 = *(const uint2*)(g_hs1b + (size_t)s0 * NHW + lane * 2);
            uint2 w1 = *(const uint2*)(g_hs1b + (size_t)s1 * NHW + lane * 2);
            uint2 w2 = *(const uint2*)(g_hs1b + (size_t)s2 * NHW + lane * 2);
            uint2 w3 = *(const uint2*)(g_hs1b + (size_t)s3 * NHW + lane * 2);
            a0 += bf_lo(w0.x) + bf_lo(w1.x) + bf_lo(w2.x) + bf_lo(w3.x);
            a1 += bf_hi(w0.x) + bf_hi(w1.x) + bf_hi(w2.x) + bf_hi(w3.x);
            a2 += bf_lo(w0.y) + bf_lo(w1.y) + bf_lo(w2.y) + bf_lo(w3.y);
            a3 += bf_hi(w0.y) + bf_hi(w1.y) + bf_hi(w2.y) + bf_hi(w3.y);
        }
        #pragma unroll 1
        for (; e < end; e++) {
            int s = g_csr[e];
            uint2 w = *(const uint2*)(g_hs1b + (size_t)s * NHW + lane * 2);
            a0 += bf_lo(w.x); a1 += bf_hi(w.x); a2 += bf_lo(w.y); a3 += bf_hi(w.y);
        }
        float z0 = fmaxf(dv * a0 + b1s[lane * 4 + 0], 0.0f);
        float z1 = fmaxf(dv * a1 + b1s[lane * 4 + 1], 0.0f);
        float z2 = fmaxf(dv * a2 + b1s[lane * 4 + 2], 0.0f);
        float z3 = fmaxf(dv * a3 + b1s[lane * 4 + 3], 0.0f);
        zsb[nl][lane * 2 + 0] = pack_bf16x2(z0, z1);
        zsb[nl][lane * 2 + 1] = pack_bf16x2(z2, z3);
    }
    __syncthreads();

    // phase B: z[32x128] @ W2[128x40] via bf16 MMA; 10 m16n8 tiles over 8 warps
    #pragma unroll 1
    for (int t = warp; t < 10; t += 8) {
        int mt = t / 5, nt = t % 5;
        float c[4] = {0.f, 0.f, 0.f, 0.f};
        #pragma unroll
        for (int ks = 0; ks < 8; ks++) {
            unsigned int a0 = zsb[mt * 16 + grp    ][ks * 8 + qid    ];
            unsigned int a1 = zsb[mt * 16 + grp + 8][ks * 8 + qid    ];
            unsigned int a2 = zsb[mt * 16 + grp    ][ks * 8 + qid + 4];
            unsigned int a3 = zsb[mt * 16 + grp + 8][ks * 8 + qid + 4];
            unsigned int b0 = W2T[nt * 8 + grp][ks * 8 + qid    ];
            unsigned int b1w = W2T[nt * 8 + grp][ks * 8 + qid + 4];
            mma_bf16(c, a0, a1, a2, a3, b0, b1w);
        }
        int n0 = blockIdx.x * 32 + mt * 16 + grp;
        int n1 = n0 + 8;
        float dv0 = dvs[mt * 16 + grp];
        float dv1 = dvs[mt * 16 + grp + 8];
        g_hs2b[(size_t)n0 * NCW + nt * 4 + qid] = pack_bf16x2(c[0] * dv0, c[1] * dv0);
        g_hs2b[(size_t)n1 * NCW + nt * 4 + qid] = pack_bf16x2(c[2] * dv1, c[3] * dv1);
    }
}

// ---- layer2: gather bf16 hs2 (self+neighbors), bias + log_softmax -> out ----
__global__ void __launch_bounds__(256)
k_layer2(const float* __restrict__ b2, float* __restrict__ out) {
    int n    = blockIdx.x * 8 + (threadIdx.x >> 5);
    int lane = threadIdx.x & 31;
    float dv = g_dinv[n];
    const bool act = lane < NCW;
    size_t baseb = (size_t)n * NCW;

    float v0 = 0.0f, v1 = 0.0f;
    if (act) {
        unsigned int w = g_hs2b[baseb + lane];
        v0 = bf_lo(w); v1 = bf_hi(w);
    }
    int beg = g_rowptr[n], end = g_rowptr[n + 1];
    int e = beg;
    #pragma unroll 1
    for (; e + 2 <= end; e += 2) {
        int s0 = g_csr[e], s1 = g_csr[e + 1];
        if (act) {
            unsigned int w0 = g_hs2b[(size_t)s0 * NCW + lane];
            unsigned int w1 = g_hs2b[(size_t)s1 * NCW + lane];
            v0 += bf_lo(w0) + bf_lo(w1);
            v1 += bf_hi(w0) + bf_hi(w1);
        }
    }
    if (e < end && act) {
        unsigned int w = g_hs2b[(size_t)g_csr[e] * NCW + lane];
        v0 += bf_lo(w); v1 += bf_hi(w);
    }

    if (act) {
        v0 = dv * v0 + b2[lane * 2];
        v1 = dv * v1 + b2[lane * 2 + 1];
    } else {
        v0 = -3.0e38f; v1 = -3.0e38f;
    }

    float m = fmaxf(v0, v1);
    #pragma unroll
    for (int off = 16; off; off >>= 1)
        m = fmaxf(m, __shfl_xor_sync(0xffffffffu, m, off));

    float ssum = act ? (expf(v0 - m) + expf(v1 - m)) : 0.0f;
    #pragma unroll
    for (int off = 16; off; off >>= 1)
        ssum += __shfl_xor_sync(0xffffffffu, ssum, off);

    float lse = m + logf(ssum);
    if (act)
        *(float2*)(out + (size_t)n * NC + lane * 2) = make_float2(v0 - lse, v1 - lse);
}

// ---------------- launch ----------------
extern "C" void kernel_launch(void* const* d_in, const int* in_sizes, int n_in,
                              void* d_out, int out_size) {
    const float* x = 0; const int* ei = 0;
    const float* W1 = 0; const float* b1 = 0;
    const float* W2 = 0; const float* b2 = 0;
    for (int i = 0; i < n_in; i++) {
        switch (in_sizes[i]) {
            case 51200000: x  = (const float*)d_in[i]; break;
            case 3200000:  ei = (const int*)d_in[i];   break;
            case 65536:    W1 = (const float*)d_in[i]; break;
            case 128:      b1 = (const float*)d_in[i]; break;
            case 5120:     W2 = (const float*)d_in[i]; break;
            case 40:       b2 = (const float*)d_in[i]; break;
        }
    }
    float* out = (float*)d_out;

    cudaFuncSetAttribute(k_gemm1, cudaFuncAttributeMaxDynamicSharedMemorySize,
                         SMEM_UINTS * 4);

    k_zero_cnt<<<(N_NODES + 255) / 256, 256>>>();
    k_deg<<<(N_EDGES + 255) / 256, 256>>>(ei);
    k_scan1<<<SCAN_NB, SCAN_CH>>>();                     // scan phase1 + dinv
    k_gemm1<<<(N_NODES + BM - 1) / BM, 256, SMEM_UINTS * 4>>>(x, W1);  // 4th = profiled
    k_scan2<<<1, 1024>>>();
    k_scan3<<<SCAN_NB, SCAN_CH>>>();
    k_fill<<<(N_EDGES + 255) / 256, 256>>>(ei);

    k_layer1<<<N_NODES / 32, 256>>>(b1, W2);
    k_layer2<<<N_NODES / 8, 256>>>(b2, out);
}

// round 13
// speedup vs baseline: 1.4165x; 1.1025x over previous
#include <cuda_runtime.h>
#include <cuda_bf16.h>
#include <math.h>

#define N_NODES 100000
#define N_EDGES 1600000
#define NF 512
#define NH 128
#define NC 40
#define NHW (NH / 2)   // 64 bf16x2 words per hs1 row
#define NCW (NC / 2)   // 20 bf16x2 words per hs2 row

#define SCAN_CH  128
#define SCAN_NB  ((N_NODES + SCAN_CH - 1) / SCAN_CH)   // 782

// ---------------- scratch (static device globals; no allocation) ----------------
__device__ __align__(16) int          g_cnt   [N_NODES];
__device__ __align__(16) int          g_rowptr[N_NODES + 1];
__device__ __align__(16) int          g_cursor[N_NODES];
__device__ __align__(16) int          g_csr   [N_EDGES];
__device__ __align__(16) int          g_bsum  [SCAN_NB];
__device__ __align__(16) int          g_boff  [SCAN_NB];
__device__ __align__(16) float        g_dinv  [N_NODES];
__device__ __align__(16) unsigned int g_hs1b  [(size_t)N_NODES * NHW]; // bf16x2
__device__ __align__(16) unsigned int g_hs2b  [(size_t)N_NODES * NCW]; // bf16x2

// ---------------- helpers ----------------
__device__ __forceinline__ void mma_bf16(float* c, unsigned int a0, unsigned int a1,
                                         unsigned int a2, unsigned int a3,
                                         unsigned int b0, unsigned int b1) {
    asm("mma.sync.aligned.m16n8k16.row.col.f32.bf16.bf16.f32 "
        "{%0,%1,%2,%3}, {%4,%5,%6,%7}, {%8,%9}, {%0,%1,%2,%3};"
        : "+f"(c[0]), "+f"(c[1]), "+f"(c[2]), "+f"(c[3])
        : "r"(a0), "r"(a1), "r"(a2), "r"(a3), "r"(b0), "r"(b1));
}
__device__ __forceinline__ unsigned int smem_u32(const void* p) {
    return (unsigned int)__cvta_generic_to_shared(p);
}
__device__ __forceinline__ void ldsm_x4(unsigned int& r0, unsigned int& r1,
                                        unsigned int& r2, unsigned int& r3,
                                        unsigned int addr) {
    asm volatile("ldmatrix.sync.aligned.m8n8.x4.shared.b16 {%0,%1,%2,%3}, [%4];"
                 : "=r"(r0), "=r"(r1), "=r"(r2), "=r"(r3) : "r"(addr));
}
__device__ __forceinline__ void ldsm_x4_t(unsigned int& r0, unsigned int& r1,
                                          unsigned int& r2, unsigned int& r3,
                                          unsigned int addr) {
    asm volatile("ldmatrix.sync.aligned.m8n8.x4.trans.shared.b16 {%0,%1,%2,%3}, [%4];"
                 : "=r"(r0), "=r"(r1), "=r"(r2), "=r"(r3) : "r"(addr));
}
__device__ __forceinline__ unsigned int pack_bf16x2(float lo, float hi) {
    unsigned int r;
    asm("cvt.rn.bf16x2.f32 %0, %1, %2;" : "=r"(r) : "f"(hi), "f"(lo));
    return r;
}
__device__ __forceinline__ float bf_lo(unsigned int w) { return __uint_as_float(w << 16); }
__device__ __forceinline__ float bf_hi(unsigned int w) { return __uint_as_float(w & 0xffff0000u); }

// ---------------- degree / dinv / CSR ----------------
__global__ void k_zero_cnt() {
    int i = blockIdx.x * blockDim.x + threadIdx.x;
    if (i < N_NODES) g_cnt[i] = 0;
}
__global__ void k_deg(const int* __restrict__ ei) {
    int e = blockIdx.x * blockDim.x + threadIdx.x;
    if (e < N_EDGES) atomicAdd(&g_cnt[ei[N_EDGES + e]], 1);
}
__global__ void __launch_bounds__(SCAN_CH) k_scan1() {
    __shared__ int wsum[4];
    const int t = threadIdx.x;
    const int i = blockIdx.x * SCAN_CH + t;
    const int lane = t & 31, warp = t >> 5;

    int v = (i < N_NODES) ? g_cnt[i] : 0;
    if (i < N_NODES) g_dinv[i] = rsqrtf((float)v + 1.0f);   // +1 self loop
    int s = v;
    #pragma unroll
    for (int off = 1; off < 32; off <<= 1) {
        int u = __shfl_up_sync(0xffffffffu, s, off);
        if (lane >= off) s += u;
    }
    if (lane == 31) wsum[warp] = s;
    __syncthreads();
    int wo = 0;
    #pragma unroll
    for (int w = 0; w < 4; w++) if (w < warp) wo += wsum[w];
    if (i < N_NODES) g_rowptr[i] = wo + s - v;
    if (t == SCAN_CH - 1) g_bsum[blockIdx.x] = wo + s;
}
__global__ void __launch_bounds__(1024) k_scan2() {
    __shared__ int sh[1024];
    const int t = threadIdx.x;
    int v = (t < SCAN_NB) ? g_bsum[t] : 0;
    sh[t] = v;
    __syncthreads();
    #pragma unroll
    for (int off = 1; off < 1024; off <<= 1) {
        int add = (t >= off) ? sh[t - off] : 0;
        __syncthreads();
        sh[t] += add;
        __syncthreads();
    }
    if (t < SCAN_NB) g_boff[t] = sh[t] - v;
    if (t == 0) g_rowptr[N_NODES] = sh[1023];
}
__global__ void __launch_bounds__(SCAN_CH) k_scan3() {
    const int i = blockIdx.x * SCAN_CH + threadIdx.x;
    if (i < N_NODES) {
        int r = g_rowptr[i] + g_boff[blockIdx.x];
        g_rowptr[i] = r;
        g_cursor[i] = r;
    }
}
__global__ void k_fill(const int* __restrict__ ei) {
    int e = blockIdx.x * blockDim.x + threadIdx.x;
    if (e < N_EDGES) {
        int s = ei[e], d = ei[N_EDGES + e];
        int pos = atomicAdd(&g_cursor[d], 1);
        g_csr[pos] = s;
    }
}

// ---------------- GEMM1 (bf16 MMA + ldmatrix, reg double-buffered) ----------------
#define BM 128
#define BK 32
#define APITCH 40    // bf16 per A row (80 B): ldmatrix 8-row banks (r*20)%32 distinct
#define BPITCH 136   // bf16 per B row (272 B): (r*68)%32 = r*4%32 distinct
__global__ void __launch_bounds__(256, 2)
k_gemm1(const float* __restrict__ X, const float* __restrict__ W1) {
    __shared__ __align__(16) __nv_bfloat16 Asm[2][BM][APITCH];  // 20 KB
    __shared__ __align__(16) __nv_bfloat16 Bsm[2][BK][BPITCH];  // 17 KB

    const int tid    = threadIdx.x;
    const int lane   = tid & 31;
    const int wid    = tid >> 5;
    const int warp_m = wid >> 2;              // 0..1 (64 rows)
    const int warp_n = wid & 3;               // 0..3 (32 cols)
    const int block_row = blockIdx.x * BM;
    const int grp = lane >> 2;                // C frag row
    const int qid = lane & 3;                 // C frag col pair

    // staging slots
    const int a_r  = tid >> 1;                // 0..127
    const int a_k0 = (tid & 1) * 16;          // 16 k per thread
    const int b_r  = tid >> 3;                // 0..31
    const int b_n0 = (tid & 7) * 16;          // 16 n per thread

    // ldmatrix lane offsets
    const int a_ro = (lane & 7) + ((lane >> 3) & 1) * 8;  // row within 16-tile
    const int a_ko = (lane >> 4) * 8;                     // k half
    const int b_ko = ((lane >> 3) & 1) * 8 + (lane & 7);  // k row within 16
    const int b_no = (lane >> 4) * 8;                     // n half

    const int  arow   = block_row + a_r;
    const bool arow_ok = arow < N_NODES;

    float acc[4][4][4];
    #pragma unroll
    for (int i = 0; i < 4; i++)
        #pragma unroll
        for (int j = 0; j < 4; j++)
            #pragma unroll
            for (int q = 0; q < 4; q++) acc[i][j][q] = 0.0f;

    float4 ar[4], br[4];
    const float4 z4 = make_float4(0.f, 0.f, 0.f, 0.f);

    auto ldg_tile = [&](int it) {
        int k0 = it * BK;
        const float* ap = X + (size_t)(arow_ok ? arow : 0) * NF + k0 + a_k0;
        #pragma unroll
        for (int j = 0; j < 4; j++)
            ar[j] = arow_ok ? __ldg((const float4*)(ap + 4 * j)) : z4;
        const float* bp = W1 + (size_t)(k0 + b_r) * NH + b_n0;
        #pragma unroll
        for (int j = 0; j < 4; j++)
            br[j] = __ldg((const float4*)(bp + 4 * j));
    };
    auto sts_tile = [&](int buf) {
        uint4 w;
        w.x = pack_bf16x2(ar[0].x, ar[0].y); w.y = pack_bf16x2(ar[0].z, ar[0].w);
        w.z = pack_bf16x2(ar[1].x, ar[1].y); w.w = pack_bf16x2(ar[1].z, ar[1].w);
        *(uint4*)&Asm[buf][a_r][a_k0] = w;
        w.x = pack_bf16x2(ar[2].x, ar[2].y); w.y = pack_bf16x2(ar[2].z, ar[2].w);
        w.z = pack_bf16x2(ar[3].x, ar[3].y); w.w = pack_bf16x2(ar[3].z, ar[3].w);
        *(uint4*)&Asm[buf][a_r][a_k0 + 8] = w;
        w.x = pack_bf16x2(br[0].x, br[0].y); w.y = pack_bf16x2(br[0].z, br[0].w);
        w.z = pack_bf16x2(br[1].x, br[1].y); w.w = pack_bf16x2(br[1].z, br[1].w);
        *(uint4*)&Bsm[buf][b_r][b_n0] = w;
        w.x = pack_bf16x2(br[2].x, br[2].y); w.y = pack_bf16x2(br[2].z, br[2].w);
        w.z = pack_bf16x2(br[3].x, br[3].y); w.w = pack_bf16x2(br[3].z, br[3].w);
        *(uint4*)&Bsm[buf][b_r][b_n0 + 8] = w;
    };

    const int NT = NF / BK;                   // 16
    ldg_tile(0);
    sts_tile(0);
    ldg_tile(1);
    __syncthreads();

    #pragma unroll 1
    for (int it = 0; it < NT; it++) {
        int cur = it & 1;
        #pragma unroll
        for (int ks = 0; ks < 2; ks++) {
            unsigned int af[4][4];
            #pragma unroll
            for (int mt = 0; mt < 4; mt++) {
                unsigned int addr = smem_u32(
                    &Asm[cur][warp_m * 64 + mt * 16 + a_ro][ks * 16 + a_ko]);
                ldsm_x4(af[mt][0], af[mt][1], af[mt][2], af[mt][3], addr);
            }
            unsigned int bfr[4][2];
            #pragma unroll
            for (int p = 0; p < 2; p++) {
                unsigned int r0, r1, r2, r3;
                unsigned int addr = smem_u32(
                    &Bsm[cur][ks * 16 + b_ko][warp_n * 32 + p * 16 + b_no]);
                ldsm_x4_t(r0, r1, r2, r3, addr);
                bfr[p * 2][0] = r0; bfr[p * 2][1] = r1;
                bfr[p * 2 + 1][0] = r2; bfr[p * 2 + 1][1] = r3;
            }
            #pragma unroll
            for (int mt = 0; mt < 4; mt++)
                #pragma unroll
                for (int nt = 0; nt < 4; nt++)
                    mma_bf16(acc[mt][nt], af[mt][0], af[mt][1], af[mt][2], af[mt][3],
                             bfr[nt][0], bfr[nt][1]);
        }
        if (it + 1 < NT) {
            sts_tile(1 - cur);
            if (it + 2 < NT) ldg_tile(it + 2);
        }
        __syncthreads();
    }

    // epilogue: scale by dinv, pack bf16x2, write hs1b
    #pragma unroll
    for (int mt = 0; mt < 4; mt++) {
        int r1 = block_row + warp_m * 64 + mt * 16 + grp;
        int r2 = r1 + 8;
        float dv1 = (r1 < N_NODES) ? g_dinv[r1] : 0.0f;
        float dv2 = (r2 < N_NODES) ? g_dinv[r2] : 0.0f;
        #pragma unroll
        for (int nt = 0; nt < 4; nt++) {
            int col = warp_n * 32 + nt * 8 + qid * 2;
            if (r1 < N_NODES)
                g_hs1b[(size_t)r1 * NHW + (col >> 1)] =
                    pack_bf16x2(acc[mt][nt][0] * dv1, acc[mt][nt][1] * dv1);
            if (r2 < N_NODES)
                g_hs1b[(size_t)r2 * NHW + (col >> 1)] =
                    pack_bf16x2(acc[mt][nt][2] * dv2, acc[mt][nt][3] * dv2);
        }
    }
}

// ---- layer1: gather bf16 hs1 -> z (smem, bf16), then block MMA z@W2 -> hs2b ----
#define Z_STRW 68
__global__ void __launch_bounds__(256)
k_layer1(const float* __restrict__ b1, const float* __restrict__ W2) {
    __shared__ unsigned int zsb[32][Z_STRW];
    __shared__ unsigned int W2T[NC][Z_STRW];
    __shared__ float b1s[NH];
    __shared__ float dvs[32];

    const int tid  = threadIdx.x;
    const int warp = tid >> 5;
    const int lane = tid & 31;
    const int grp  = lane >> 2;
    const int qid  = lane & 3;

    #pragma unroll
    for (int i = tid; i < NC * 64; i += 256) {
        int n = i >> 6, w = i & 63;
        W2T[n][w] = pack_bf16x2(W2[(2 * w) * NC + n], W2[(2 * w + 1) * NC + n]);
    }
    if (tid < NH) b1s[tid] = b1[tid];
    __syncthreads();

    #pragma unroll 1
    for (int it = 0; it < 4; it++) {
        int nl = it * 8 + warp;
        int n  = blockIdx.x * 32 + nl;
        float dv = g_dinv[n];
        if (lane == 0) dvs[nl] = dv;

        uint2 sw = *(const uint2*)(g_hs1b + (size_t)n * NHW + lane * 2);
        float a0 = bf_lo(sw.x), a1 = bf_hi(sw.x), a2 = bf_lo(sw.y), a3 = bf_hi(sw.y);

        int beg = g_rowptr[n], end = g_rowptr[n + 1];
        int e = beg;
        #pragma unroll 1
        for (; e + 4 <= end; e += 4) {
            int s0 = g_csr[e], s1 = g_csr[e + 1], s2 = g_csr[e + 2], s3 = g_csr[e + 3];
            uint2 w0 = *(const uint2*)(g_hs1b + (size_t)s0 * NHW + lane * 2);
            uint2 w1 = *(const uint2*)(g_hs1b + (size_t)s1 * NHW + lane * 2);
            uint2 w2 = *(const uint2*)(g_hs1b + (size_t)s2 * NHW + lane * 2);
            uint2 w3 = *(const uint2*)(g_hs1b + (size_t)s3 * NHW + lane * 2);
            a0 += bf_lo(w0.x) + bf_lo(w1.x) + bf_lo(w2.x) + bf_lo(w3.x);
            a1 += bf_hi(w0.x) + bf_hi(w1.x) + bf_hi(w2.x) + bf_hi(w3.x);
            a2 += bf_lo(w0.y) + bf_lo(w1.y) + bf_lo(w2.y) + bf_lo(w3.y);
            a3 += bf_hi(w0.y) + bf_hi(w1.y) + bf_hi(w2.y) + bf_hi(w3.y);
        }
        #pragma unroll 1
        for (; e < end; e++) {
            int s = g_csr[e];
            uint2 w = *(const uint2*)(g_hs1b + (size_t)s * NHW + lane * 2);
            a0 += bf_lo(w.x); a1 += bf_hi(w.x); a2 += bf_lo(w.y); a3 += bf_hi(w.y);
        }
        float z0 = fmaxf(dv * a0 + b1s[lane * 4 + 0], 0.0f);
        float z1 = fmaxf(dv * a1 + b1s[lane * 4 + 1], 0.0f);
        float z2 = fmaxf(dv * a2 + b1s[lane * 4 + 2], 0.0f);
        float z3 = fmaxf(dv * a3 + b1s[lane * 4 + 3], 0.0f);
        zsb[nl][lane * 2 + 0] = pack_bf16x2(z0, z1);
        zsb[nl][lane * 2 + 1] = pack_bf16x2(z2, z3);
    }
    __syncthreads();

    #pragma unroll 1
    for (int t = warp; t < 10; t += 8) {
        int mt = t / 5, nt = t % 5;
        float c[4] = {0.f, 0.f, 0.f, 0.f};
        #pragma unroll
        for (int ks = 0; ks < 8; ks++) {
            unsigned int a0 = zsb[mt * 16 + grp    ][ks * 8 + qid    ];
            unsigned int a1 = zsb[mt * 16 + grp + 8][ks * 8 + qid    ];
            unsigned int a2 = zsb[mt * 16 + grp    ][ks * 8 + qid + 4];
            unsigned int a3 = zsb[mt * 16 + grp + 8][ks * 8 + qid + 4];
            unsigned int b0 = W2T[nt * 8 + grp][ks * 8 + qid    ];
            unsigned int b1w = W2T[nt * 8 + grp][ks * 8 + qid + 4];
            mma_bf16(c, a0, a1, a2, a3, b0, b1w);
        }
        int n0 = blockIdx.x * 32 + mt * 16 + grp;
        int n1 = n0 + 8;
        float dv0 = dvs[mt * 16 + grp];
        float dv1 = dvs[mt * 16 + grp + 8];
        g_hs2b[(size_t)n0 * NCW + nt * 4 + qid] = pack_bf16x2(c[0] * dv0, c[1] * dv0);
        g_hs2b[(size_t)n1 * NCW + nt * 4 + qid] = pack_bf16x2(c[2] * dv1, c[3] * dv1);
    }
}

// ---- layer2: gather bf16 hs2 (self+neighbors), bias + log_softmax -> out ----
__global__ void __launch_bounds__(256)
k_layer2(const float* __restrict__ b2, float* __restrict__ out) {
    int n    = blockIdx.x * 8 + (threadIdx.x >> 5);
    int lane = threadIdx.x & 31;
    float dv = g_dinv[n];
    const bool act = lane < NCW;
    size_t baseb = (size_t)n * NCW;

    float v0 = 0.0f, v1 = 0.0f;
    if (act) {
        unsigned int w = g_hs2b[baseb + lane];
        v0 = bf_lo(w); v1 = bf_hi(w);
    }
    int beg = g_rowptr[n], end = g_rowptr[n + 1];
    int e = beg;
    #pragma unroll 1
    for (; e + 2 <= end; e += 2) {
        int s0 = g_csr[e], s1 = g_csr[e + 1];
        if (act) {
            unsigned int w0 = g_hs2b[(size_t)s0 * NCW + lane];
            unsigned int w1 = g_hs2b[(size_t)s1 * NCW + lane];
            v0 += bf_lo(w0) + bf_lo(w1);
            v1 += bf_hi(w0) + bf_hi(w1);
        }
    }
    if (e < end && act) {
        unsigned int w = g_hs2b[(size_t)g_csr[e] * NCW + lane];
        v0 += bf_lo(w); v1 += bf_hi(w);
    }

    if (act) {
        v0 = dv * v0 + b2[lane * 2];
        v1 = dv * v1 + b2[lane * 2 + 1];
    } else {
        v0 = -3.0e38f; v1 = -3.0e38f;
    }

    float m = fmaxf(v0, v1);
    #pragma unroll
    for (int off = 16; off; off >>= 1)
        m = fmaxf(m, __shfl_xor_sync(0xffffffffu, m, off));

    float ssum = act ? (expf(v0 - m) + expf(v1 - m)) : 0.0f;
    #pragma unroll
    for (int off = 16; off; off >>= 1)
        ssum += __shfl_xor_sync(0xffffffffu, ssum, off);

    float lse = m + logf(ssum);
    if (act)
        *(float2*)(out + (size_t)n * NC + lane * 2) = make_float2(v0 - lse, v1 - lse);
}

// ---------------- launch ----------------
extern "C" void kernel_launch(void* const* d_in, const int* in_sizes, int n_in,
                              void* d_out, int out_size) {
    const float* x = 0; const int* ei = 0;
    const float* W1 = 0; const float* b1 = 0;
    const float* W2 = 0; const float* b2 = 0;
    for (int i = 0; i < n_in; i++) {
        switch (in_sizes[i]) {
            case 51200000: x  = (const float*)d_in[i]; break;
            case 3200000:  ei = (const int*)d_in[i];   break;
            case 65536:    W1 = (const float*)d_in[i]; break;
            case 128:      b1 = (const float*)d_in[i]; break;
            case 5120:     W2 = (const float*)d_in[i]; break;
            case 40:       b2 = (const float*)d_in[i]; break;
        }
    }
    float* out = (float*)d_out;

    k_zero_cnt<<<(N_NODES + 255) / 256, 256>>>();
    k_deg<<<(N_EDGES + 255) / 256, 256>>>(ei);
    k_scan1<<<SCAN_NB, SCAN_CH>>>();                     // scan phase1 + dinv
    k_gemm1<<<(N_NODES + BM - 1) / BM, 256>>>(x, W1);    // 4th = profiled
    k_scan2<<<1, 1024>>>();
    k_scan3<<<SCAN_NB, SCAN_CH>>>();
    k_fill<<<(N_EDGES + 255) / 256, 256>>>(ei);

    k_layer1<<<N_NODES / 32, 256>>>(b1, W2);
    k_layer2<<<N_NODES / 8, 256>>>(b2, out);
}

// round 15
// speedup vs baseline: 1.6266x; 1.1483x over previous
#include <cuda_runtime.h>
#include <cuda_bf16.h>
#include <math.h>

#define N_NODES 100000
#define N_EDGES 1600000
#define NF 512
#define NH 128
#define NC 40
#define NHW (NH / 2)   // 64 bf16x2 words per hs1 row
#define NCW (NC / 2)   // 20 bf16x2 words per hs2 row

#define SCAN_CH  128
#define SCAN_NB  ((N_NODES + SCAN_CH - 1) / SCAN_CH)   // 782

// ---------------- scratch (static device globals; no allocation) ----------------
__device__ __align__(16) int          g_cnt   [N_NODES];
__device__ __align__(16) int          g_rowptr[N_NODES + 1];
__device__ __align__(16) int          g_cursor[N_NODES];
__device__ __align__(16) int          g_csr   [N_EDGES];
__device__ __align__(16) int          g_bsum  [SCAN_NB];
__device__ __align__(16) int          g_boff  [SCAN_NB];
__device__ __align__(16) float        g_dinv  [N_NODES];
__device__ __align__(16) unsigned int g_hs1b  [(size_t)N_NODES * NHW]; // bf16x2
__device__ __align__(16) unsigned int g_hs2b  [(size_t)N_NODES * NCW]; // bf16x2
__device__ __align__(16) unsigned int g_w1bf  [NF * NH / 2];           // W1 bf16x2 [k][n]

// ---------------- helpers ----------------
__device__ __forceinline__ void mma_bf16(float* c, unsigned int a0, unsigned int a1,
                                         unsigned int a2, unsigned int a3,
                                         unsigned int b0, unsigned int b1) {
    asm("mma.sync.aligned.m16n8k16.row.col.f32.bf16.bf16.f32 "
        "{%0,%1,%2,%3}, {%4,%5,%6,%7}, {%8,%9}, {%0,%1,%2,%3};"
        : "+f"(c[0]), "+f"(c[1]), "+f"(c[2]), "+f"(c[3])
        : "r"(a0), "r"(a1), "r"(a2), "r"(a3), "r"(b0), "r"(b1));
}
__device__ __forceinline__ unsigned int smem_u32(const void* p) {
    return (unsigned int)__cvta_generic_to_shared(p);
}
__device__ __forceinline__ void ldsm_x4(unsigned int& r0, unsigned int& r1,
                                        unsigned int& r2, unsigned int& r3,
                                        unsigned int addr) {
    asm volatile("ldmatrix.sync.aligned.m8n8.x4.shared.b16 {%0,%1,%2,%3}, [%4];"
                 : "=r"(r0), "=r"(r1), "=r"(r2), "=r"(r3) : "r"(addr));
}
__device__ __forceinline__ void ldsm_x4_t(unsigned int& r0, unsigned int& r1,
                                          unsigned int& r2, unsigned int& r3,
                                          unsigned int addr) {
    asm volatile("ldmatrix.sync.aligned.m8n8.x4.trans.shared.b16 {%0,%1,%2,%3}, [%4];"
                 : "=r"(r0), "=r"(r1), "=r"(r2), "=r"(r3) : "r"(addr));
}
__device__ __forceinline__ unsigned int pack_bf16x2(float lo, float hi) {
    unsigned int r;
    asm("cvt.rn.bf16x2.f32 %0, %1, %2;" : "=r"(r) : "f"(hi), "f"(lo));
    return r;
}
__device__ __forceinline__ float bf_lo(unsigned int w) { return __uint_as_float(w << 16); }
__device__ __forceinline__ float bf_hi(unsigned int w) { return __uint_as_float(w & 0xffff0000u); }

// ---------------- prep: zero cnt + pack W1 to bf16x2 ----------------
__global__ void k_prep(const float* __restrict__ W1) {
    int i = blockIdx.x * blockDim.x + threadIdx.x;
    if (i < N_NODES) g_cnt[i] = 0;
    if (i < NF * NH / 2) {                    // 32768 words
        int k = i >> 6, w = i & 63;
        g_w1bf[i] = pack_bf16x2(W1[(size_t)k * NH + 2 * w], W1[(size_t)k * NH + 2 * w + 1]);
    }
}
__global__ void k_deg(const int* __restrict__ ei) {
    int e = blockIdx.x * blockDim.x + threadIdx.x;
    if (e < N_EDGES) atomicAdd(&g_cnt[ei[N_EDGES + e]], 1);
}
__global__ void __launch_bounds__(SCAN_CH) k_scan1() {
    __shared__ int wsum[4];
    const int t = threadIdx.x;
    const int i = blockIdx.x * SCAN_CH + t;
    const int lane = t & 31, warp = t >> 5;

    int v = (i < N_NODES) ? g_cnt[i] : 0;
    if (i < N_NODES) g_dinv[i] = rsqrtf((float)v + 1.0f);   // +1 self loop
    int s = v;
    #pragma unroll
    for (int off = 1; off < 32; off <<= 1) {
        int u = __shfl_up_sync(0xffffffffu, s, off);
        if (lane >= off) s += u;
    }
    if (lane == 31) wsum[warp] = s;
    __syncthreads();
    int wo = 0;
    #pragma unroll
    for (int w = 0; w < 4; w++) if (w < warp) wo += wsum[w];
    if (i < N_NODES) g_rowptr[i] = wo + s - v;
    if (t == SCAN_CH - 1) g_bsum[blockIdx.x] = wo + s;
}
__global__ void __launch_bounds__(1024) k_scan2() {
    __shared__ int sh[1024];
    const int t = threadIdx.x;
    int v = (t < SCAN_NB) ? g_bsum[t] : 0;
    sh[t] = v;
    __syncthreads();
    #pragma unroll
    for (int off = 1; off < 1024; off <<= 1) {
        int add = (t >= off) ? sh[t - off] : 0;
        __syncthreads();
        sh[t] += add;
        __syncthreads();
    }
    if (t < SCAN_NB) g_boff[t] = sh[t] - v;
    if (t == 0) g_rowptr[N_NODES] = sh[1023];
}
__global__ void __launch_bounds__(SCAN_CH) k_scan3() {
    const int i = blockIdx.x * SCAN_CH + threadIdx.x;
    if (i < N_NODES) {
        int r = g_rowptr[i] + g_boff[blockIdx.x];
        g_rowptr[i] = r;
        g_cursor[i] = r;
    }
}
__global__ void k_fill(const int* __restrict__ ei) {
    int e = blockIdx.x * blockDim.x + threadIdx.x;
    if (e < N_EDGES) {
        int s = ei[e], d = ei[N_EDGES + e];
        int pos = atomicAdd(&g_cursor[d], 1);
        g_csr[pos] = s;
    }
}

// ---------------- GEMM1 (bf16 MMA + ldmatrix, reg double-buffered) ----------------
#define BM 128
#define BK 32
#define APITCH 40    // bf16 per A row (80 B)
#define BPITCH 136   // bf16 per B row (272 B)
__global__ void __launch_bounds__(256, 2)
k_gemm1(const float* __restrict__ X) {
    __shared__ __align__(16) __nv_bfloat16 Asm[2][BM][APITCH];  // 20 KB
    __shared__ __align__(16) __nv_bfloat16 Bsm[2][BK][BPITCH];  // 17 KB

    const int tid    = threadIdx.x;
    const int lane   = tid & 31;
    const int wid    = tid >> 5;
    const int warp_m = wid >> 2;              // 0..1 (64 rows)
    const int warp_n = wid & 3;               // 0..3 (32 cols)
    const int block_row = blockIdx.x * BM;
    const int grp = lane >> 2;
    const int qid = lane & 3;

    // staging slots
    const int a_r  = tid >> 1;                // 0..127
    const int a_k0 = (tid & 1) * 16;          // 16 k per thread
    const int b_r  = tid >> 3;                // 0..31
    const int b_c  = tid & 7;                 // uint4 chunks b_c, b_c+8

    // ldmatrix lane offsets
    const int a_ro = (lane & 7) + ((lane >> 3) & 1) * 8;
    const int a_ko = (lane >> 4) * 8;
    const int b_ko = ((lane >> 3) & 1) * 8 + (lane & 7);
    const int b_no = (lane >> 4) * 8;

    const int  arow    = block_row + a_r;
    const bool arow_ok = arow < N_NODES;

    float acc[4][4][4];
    #pragma unroll
    for (int i = 0; i < 4; i++)
        #pragma unroll
        for (int j = 0; j < 4; j++)
            #pragma unroll
            for (int q = 0; q < 4; q++) acc[i][j][q] = 0.0f;

    float4 ar[4];
    uint4  br[2];
    const float4 z4 = make_float4(0.f, 0.f, 0.f, 0.f);
    const uint4* W1b4 = (const uint4*)g_w1bf;     // row k = 16 uint4

    auto ldg_tile = [&](int it) {
        int k0 = it * BK;
        const float* ap = X + (size_t)(arow_ok ? arow : 0) * NF + k0 + a_k0;
        #pragma unroll
        for (int j = 0; j < 4; j++)
            ar[j] = arow_ok ? __ldg((const float4*)(ap + 4 * j)) : z4;
        const uint4* bp = W1b4 + (size_t)(k0 + b_r) * 16;
        br[0] = __ldg(bp + b_c);
        br[1] = __ldg(bp + b_c + 8);
    };
    auto sts_tile = [&](int buf) {
        uint4 w;
        w.x = pack_bf16x2(ar[0].x, ar[0].y); w.y = pack_bf16x2(ar[0].z, ar[0].w);
        w.z = pack_bf16x2(ar[1].x, ar[1].y); w.w = pack_bf16x2(ar[1].z, ar[1].w);
        *(uint4*)&Asm[buf][a_r][a_k0] = w;
        w.x = pack_bf16x2(ar[2].x, ar[2].y); w.y = pack_bf16x2(ar[2].z, ar[2].w);
        w.z = pack_bf16x2(ar[3].x, ar[3].y); w.w = pack_bf16x2(ar[3].z, ar[3].w);
        *(uint4*)&Asm[buf][a_r][a_k0 + 8] = w;
        *(uint4*)&Bsm[buf][b_r][b_c * 8]      = br[0];
        *(uint4*)&Bsm[buf][b_r][b_c * 8 + 64] = br[1];
    };

    const int NT = NF / BK;                   // 16
    ldg_tile(0);
    sts_tile(0);
    ldg_tile(1);
    __syncthreads();

    #pragma unroll 1
    for (int it = 0; it < NT; it++) {
        int cur = it & 1;
        #pragma unroll
        for (int ks = 0; ks < 2; ks++) {
            unsigned int af[4][4];
            #pragma unroll
            for (int mt = 0; mt < 4; mt++) {
                unsigned int addr = smem_u32(
                    &Asm[cur][warp_m * 64 + mt * 16 + a_ro][ks * 16 + a_ko]);
                ldsm_x4(af[mt][0], af[mt][1], af[mt][2], af[mt][3], addr);
            }
            unsigned int bfr[4][2];
            #pragma unroll
            for (int p = 0; p < 2; p++) {
                unsigned int r0, r1, r2, r3;
                unsigned int addr = smem_u32(
                    &Bsm[cur][ks * 16 + b_ko][warp_n * 32 + p * 16 + b_no]);
                ldsm_x4_t(r0, r1, r2, r3, addr);
                bfr[p * 2][0] = r0; bfr[p * 2][1] = r1;
                bfr[p * 2 + 1][0] = r2; bfr[p * 2 + 1][1] = r3;
            }
            #pragma unroll
            for (int mt = 0; mt < 4; mt++)
                #pragma unroll
                for (int nt = 0; nt < 4; nt++)
                    mma_bf16(acc[mt][nt], af[mt][0], af[mt][1], af[mt][2], af[mt][3],
                             bfr[nt][0], bfr[nt][1]);
        }
        if (it + 1 < NT) {
            sts_tile(1 - cur);
            if (it + 2 < NT) ldg_tile(it + 2);
        }
        __syncthreads();
    }

    // epilogue: scale by dinv, pack bf16x2, write hs1b
    #pragma unroll
    for (int mt = 0; mt < 4; mt++) {
        int r1 = block_row + warp_m * 64 + mt * 16 + grp;
        int r2 = r1 + 8;
        float dv1 = (r1 < N_NODES) ? g_dinv[r1] : 0.0f;
        float dv2 = (r2 < N_NODES) ? g_dinv[r2] : 0.0f;
        #pragma unroll
        for (int nt = 0; nt < 4; nt++) {
            int col = warp_n * 32 + nt * 8 + qid * 2;
            if (r1 < N_NODES)
                g_hs1b[(size_t)r1 * NHW + (col >> 1)] =
                    pack_bf16x2(acc[mt][nt][0] * dv1, acc[mt][nt][1] * dv1);
            if (r2 < N_NODES)
                g_hs1b[(size_t)r2 * NHW + (col >> 1)] =
                    pack_bf16x2(acc[mt][nt][2] * dv2, acc[mt][nt][3] * dv2);
        }
    }
}

// ---- layer1: gather bf16 hs1 -> z (smem, bf16), then block MMA z@W2 -> hs2b ----
#define Z_STRW 68
__global__ void __launch_bounds__(256)
k_layer1(const float* __restrict__ b1, const float* __restrict__ W2) {
    __shared__ unsigned int zsb[32][Z_STRW];
    __shared__ unsigned int W2T[NC][Z_STRW];
    __shared__ float b1s[NH];
    __shared__ float dvs[32];

    const int tid  = threadIdx.x;
    const int warp = tid >> 5;
    const int lane = tid & 31;
    const int grp  = lane >> 2;
    const int qid  = lane & 3;

    #pragma unroll
    for (int i = tid; i < NC * 64; i += 256) {
        int n = i >> 6, w = i & 63;
        W2T[n][w] = pack_bf16x2(W2[(2 * w) * NC + n], W2[(2 * w + 1) * NC + n]);
    }
    if (tid < NH) b1s[tid] = b1[tid];
    __syncthreads();

    #pragma unroll 1
    for (int it = 0; it < 4; it++) {
        int nl = it * 8 + warp;
        int n  = blockIdx.x * 32 + nl;
        float dv = g_dinv[n];
        if (lane == 0) dvs[nl] = dv;

        uint2 sw = *(const uint2*)(g_hs1b + (size_t)n * NHW + lane * 2);
        float a0 = bf_lo(sw.x), a1 = bf_hi(sw.x), a2 = bf_lo(sw.y), a3 = bf_hi(sw.y);

        int beg = g_rowptr[n], end = g_rowptr[n + 1];
        // coalesced index load (32 at a time) + shfl distribution
        #pragma unroll 1
        for (int base = beg; base < end; base += 32) {
            int cnt = end - base; if (cnt > 32) cnt = 32;
            int idx = (base + lane < end) ? g_csr[base + lane] : 0;
            int j = 0;
            #pragma unroll 1
            for (; j + 4 <= cnt; j += 4) {
                int s0 = __shfl_sync(0xffffffffu, idx, j);
                int s1 = __shfl_sync(0xffffffffu, idx, j + 1);
                int s2 = __shfl_sync(0xffffffffu, idx, j + 2);
                int s3 = __shfl_sync(0xffffffffu, idx, j + 3);
                uint2 w0 = *(const uint2*)(g_hs1b + (size_t)s0 * NHW + lane * 2);
                uint2 w1 = *(const uint2*)(g_hs1b + (size_t)s1 * NHW + lane * 2);
                uint2 w2 = *(const uint2*)(g_hs1b + (size_t)s2 * NHW + lane * 2);
                uint2 w3 = *(const uint2*)(g_hs1b + (size_t)s3 * NHW + lane * 2);
                a0 += bf_lo(w0.x) + bf_lo(w1.x) + bf_lo(w2.x) + bf_lo(w3.x);
                a1 += bf_hi(w0.x) + bf_hi(w1.x) + bf_hi(w2.x) + bf_hi(w3.x);
                a2 += bf_lo(w0.y) + bf_lo(w1.y) + bf_lo(w2.y) + bf_lo(w3.y);
                a3 += bf_hi(w0.y) + bf_hi(w1.y) + bf_hi(w2.y) + bf_hi(w3.y);
            }
            #pragma unroll 1
            for (; j < cnt; j++) {
                int s = __shfl_sync(0xffffffffu, idx, j);
                uint2 w = *(const uint2*)(g_hs1b + (size_t)s * NHW + lane * 2);
                a0 += bf_lo(w.x); a1 += bf_hi(w.x); a2 += bf_lo(w.y); a3 += bf_hi(w.y);
            }
        }
        float z0 = fmaxf(dv * a0 + b1s[lane * 4 + 0], 0.0f);
        float z1 = fmaxf(dv * a1 + b1s[lane * 4 + 1], 0.0f);
        float z2 = fmaxf(dv * a2 + b1s[lane * 4 + 2], 0.0f);
        float z3 = fmaxf(dv * a3 + b1s[lane * 4 + 3], 0.0f);
        zsb[nl][lane * 2 + 0] = pack_bf16x2(z0, z1);
        zsb[nl][lane * 2 + 1] = pack_bf16x2(z2, z3);
    }
    __syncthreads();

    #pragma unroll 1
    for (int t = warp; t < 10; t += 8) {
        int mt = t / 5, nt = t % 5;
        float c[4] = {0.f, 0.f, 0.f, 0.f};
        #pragma unroll
        for (int ks = 0; ks < 8; ks++) {
            unsigned int a0 = zsb[mt * 16 + grp    ][ks * 8 + qid    ];
            unsigned int a1 = zsb[mt * 16 + grp + 8][ks * 8 + qid    ];
            unsigned int a2 = zsb[mt * 16 + grp    ][ks * 8 + qid + 4];
            unsigned int a3 = zsb[mt * 16 + grp + 8][ks * 8 + qid + 4];
            unsigned int b0 = W2T[nt * 8 + grp][ks * 8 + qid    ];
            unsigned int b1w = W2T[nt * 8 + grp][ks * 8 + qid + 4];
            mma_bf16(c, a0, a1, a2, a3, b0, b1w);
        }
        int n0 = blockIdx.x * 32 + mt * 16 + grp;
        int n1 = n0 + 8;
        float dv0 = dvs[mt * 16 + grp];
        float dv1 = dvs[mt * 16 + grp + 8];
        g_hs2b[(size_t)n0 * NCW + nt * 4 + qid] = pack_bf16x2(c[0] * dv0, c[1] * dv0);
        g_hs2b[(size_t)n1 * NCW + nt * 4 + qid] = pack_bf16x2(c[2] * dv1, c[3] * dv1);
    }
}

// ---- layer2: gather bf16 hs2 (self+neighbors), bias + log_softmax -> out ----
__global__ void __launch_bounds__(256)
k_layer2(const float* __restrict__ b2, float* __restrict__ out) {
    int n    = blockIdx.x * 8 + (threadIdx.x >> 5);
    int lane = threadIdx.x & 31;
    float dv = g_dinv[n];
    const bool act = lane < NCW;
    size_t baseb = (size_t)n * NCW;

    float v0 = 0.0f, v1 = 0.0f;
    if (act) {
        unsigned int w = g_hs2b[baseb + lane];
        v0 = bf_lo(w); v1 = bf_hi(w);
    }
    int beg = g_rowptr[n], end = g_rowptr[n + 1];
    #pragma unroll 1
    for (int base = beg; base < end; base += 32) {
        int cnt = end - base; if (cnt > 32) cnt = 32;
        int idx = (base + lane < end) ? g_csr[base + lane] : 0;
        int j = 0;
        #pragma unroll 1
        for (; j + 2 <= cnt; j += 2) {
            int s0 = __shfl_sync(0xffffffffu, idx, j);
            int s1 = __shfl_sync(0xffffffffu, idx, j + 1);
            if (act) {
                unsigned int w0 = g_hs2b[(size_t)s0 * NCW + lane];
                unsigned int w1 = g_hs2b[(size_t)s1 * NCW + lane];
                v0 += bf_lo(w0) + bf_lo(w1);
                v1 += bf_hi(w0) + bf_hi(w1);
            }
        }
        if (j < cnt) {
            int s = __shfl_sync(0xffffffffu, idx, j);
            if (act) {
                unsigned int w = g_hs2b[(size_t)s * NCW + lane];
                v0 += bf_lo(w); v1 += bf_hi(w);
            }
        }
    }

    if (act) {
        v0 = dv * v0 + b2[lane * 2];
        v1 = dv * v1 + b2[lane * 2 + 1];
    } else {
        v0 = -3.0e38f; v1 = -3.0e38f;
    }

    float m = fmaxf(v0, v1);
    #pragma unroll
    for (int off = 16; off; off >>= 1)
        m = fmaxf(m, __shfl_xor_sync(0xffffffffu, m, off));

    float ssum = act ? (expf(v0 - m) + expf(v1 - m)) : 0.0f;
    #pragma unroll
    for (int off = 16; off; off >>= 1)
        ssum += __shfl_xor_sync(0xffffffffu, ssum, off);

    float lse = m + logf(ssum);
    if (act)
        *(float2*)(out + (size_t)n * NC + lane * 2) = make_float2(v0 - lse, v1 - lse);
}

// ---------------- launch ----------------
extern "C" void kernel_launch(void* const* d_in, const int* in_sizes, int n_in,
                              void* d_out, int out_size) {
    const float* x = 0; const int* ei = 0;
    const float* W1 = 0; const float* b1 = 0;
    const float* W2 = 0; const float* b2 = 0;
    for (int i = 0; i < n_in; i++) {
        switch (in_sizes[i]) {
            case 51200000: x  = (const float*)d_in[i]; break;
            case 3200000:  ei = (const int*)d_in[i];   break;
            case 65536:    W1 = (const float*)d_in[i]; break;
            case 128:      b1 = (const float*)d_in[i]; break;
            case 5120:     W2 = (const float*)d_in[i]; break;
            case 40:       b2 = (const float*)d_in[i]; break;
        }
    }
    float* out = (float*)d_out;

    k_prep<<<(N_NODES + 255) / 256, 256>>>(W1);          // zero cnt + pack W1 bf16
    k_deg<<<(N_EDGES + 255) / 256, 256>>>(ei);
    k_scan1<<<SCAN_NB, SCAN_CH>>>();                     // scan phase1 + dinv
    k_gemm1<<<(N_NODES + BM - 1) / BM, 256>>>(x);        // 4th = profiled
    k_scan2<<<1, 1024>>>();
    k_scan3<<<SCAN_NB, SCAN_CH>>>();
    k_fill<<<(N_EDGES + 255) / 256, 256>>>(ei);

    k_layer1<<<N_NODES / 32, 256>>>(b1, W2);
    k_layer2<<<N_NODES / 8, 256>>>(b2, out);
}

// round 16
// speedup vs baseline: 1.6409x; 1.0088x over previous
#include <cuda_runtime.h>
#include <cuda_bf16.h>
#include <math.h>

#define N_NODES 100000
#define N_EDGES 1600000
#define NF 512
#define NH 128
#define NC 40
#define NHW (NH / 2)   // 64 bf16x2 words per hs1 row
#define NCW (NC / 2)   // 20 bf16x2 words per hs2 row

#define SCAN_CH  128
#define SCAN_NB  ((N_NODES + SCAN_CH - 1) / SCAN_CH)   // 782

// ---------------- scratch (static device globals; no allocation) ----------------
__device__ __align__(16) int          g_cnt   [N_NODES];
__device__ __align__(16) int          g_rowptr[N_NODES + 1];
__device__ __align__(16) int          g_cursor[N_NODES];
__device__ __align__(16) int          g_csr   [N_EDGES];
__device__ __align__(16) int          g_bsum  [SCAN_NB];
__device__ __align__(16) int          g_boff  [SCAN_NB];
__device__ __align__(16) float        g_dinv  [N_NODES];
__device__ __align__(16) unsigned int g_hs1b  [(size_t)N_NODES * NHW]; // bf16x2
__device__ __align__(16) unsigned int g_hs2b  [(size_t)N_NODES * NCW]; // bf16x2
__device__ __align__(16) unsigned int g_w1bf  [NF * NH / 2];           // W1 bf16x2 [k][n]

// ---------------- helpers ----------------
__device__ __forceinline__ void mma_bf16(float* c, unsigned int a0, unsigned int a1,
                                         unsigned int a2, unsigned int a3,
                                         unsigned int b0, unsigned int b1) {
    asm("mma.sync.aligned.m16n8k16.row.col.f32.bf16.bf16.f32 "
        "{%0,%1,%2,%3}, {%4,%5,%6,%7}, {%8,%9}, {%0,%1,%2,%3};"
        : "+f"(c[0]), "+f"(c[1]), "+f"(c[2]), "+f"(c[3])
        : "r"(a0), "r"(a1), "r"(a2), "r"(a3), "r"(b0), "r"(b1));
}
__device__ __forceinline__ unsigned int smem_u32(const void* p) {
    return (unsigned int)__cvta_generic_to_shared(p);
}
__device__ __forceinline__ void ldsm_x4(unsigned int& r0, unsigned int& r1,
                                        unsigned int& r2, unsigned int& r3,
                                        unsigned int addr) {
    asm volatile("ldmatrix.sync.aligned.m8n8.x4.shared.b16 {%0,%1,%2,%3}, [%4];"
                 : "=r"(r0), "=r"(r1), "=r"(r2), "=r"(r3) : "r"(addr));
}
__device__ __forceinline__ void ldsm_x4_t(unsigned int& r0, unsigned int& r1,
                                          unsigned int& r2, unsigned int& r3,
                                          unsigned int addr) {
    asm volatile("ldmatrix.sync.aligned.m8n8.x4.trans.shared.b16 {%0,%1,%2,%3}, [%4];"
                 : "=r"(r0), "=r"(r1), "=r"(r2), "=r"(r3) : "r"(addr));
}
__device__ __forceinline__ unsigned int pack_bf16x2(float lo, float hi) {
    unsigned int r;
    asm("cvt.rn.bf16x2.f32 %0, %1, %2;" : "=r"(r) : "f"(hi), "f"(lo));
    return r;
}
__device__ __forceinline__ float bf_lo(unsigned int w) { return __uint_as_float(w << 16); }
__device__ __forceinline__ float bf_hi(unsigned int w) { return __uint_as_float(w & 0xffff0000u); }

// ---------------- prep: zero cnt + pack W1 to bf16x2 ----------------
__global__ void k_prep(const float* __restrict__ W1) {
    int i = blockIdx.x * blockDim.x + threadIdx.x;
    if (i < N_NODES) g_cnt[i] = 0;
    if (i < NF * NH / 2) {                    // 32768 words
        int k = i >> 6, w = i & 63;
        g_w1bf[i] = pack_bf16x2(W1[(size_t)k * NH + 2 * w], W1[(size_t)k * NH + 2 * w + 1]);
    }
}
__global__ void k_deg(const int* __restrict__ ei) {
    int e = blockIdx.x * blockDim.x + threadIdx.x;
    if (e < N_EDGES) atomicAdd(&g_cnt[ei[N_EDGES + e]], 1);
}
__global__ void __launch_bounds__(SCAN_CH) k_scan1() {
    __shared__ int wsum[4];
    const int t = threadIdx.x;
    const int i = blockIdx.x * SCAN_CH + t;
    const int lane = t & 31, warp = t >> 5;

    int v = (i < N_NODES) ? g_cnt[i] : 0;
    if (i < N_NODES) g_dinv[i] = rsqrtf((float)v + 1.0f);   // +1 self loop
    int s = v;
    #pragma unroll
    for (int off = 1; off < 32; off <<= 1) {
        int u = __shfl_up_sync(0xffffffffu, s, off);
        if (lane >= off) s += u;
    }
    if (lane == 31) wsum[warp] = s;
    __syncthreads();
    int wo = 0;
    #pragma unroll
    for (int w = 0; w < 4; w++) if (w < warp) wo += wsum[w];
    if (i < N_NODES) g_rowptr[i] = wo + s - v;
    if (t == SCAN_CH - 1) g_bsum[blockIdx.x] = wo + s;
}
__global__ void __launch_bounds__(1024) k_scan2() {
    __shared__ int sh[1024];
    const int t = threadIdx.x;
    int v = (t < SCAN_NB) ? g_bsum[t] : 0;
    sh[t] = v;
    __syncthreads();
    #pragma unroll
    for (int off = 1; off < 1024; off <<= 1) {
        int add = (t >= off) ? sh[t - off] : 0;
        __syncthreads();
        sh[t] += add;
        __syncthreads();
    }
    if (t < SCAN_NB) g_boff[t] = sh[t] - v;
    if (t == 0) g_rowptr[N_NODES] = sh[1023];
}
__global__ void __launch_bounds__(SCAN_CH) k_scan3() {
    const int i = blockIdx.x * SCAN_CH + threadIdx.x;
    if (i < N_NODES) {
        int r = g_rowptr[i] + g_boff[blockIdx.x];
        g_rowptr[i] = r;
        g_cursor[i] = r;
    }
}
__global__ void k_fill(const int* __restrict__ ei) {
    int e = blockIdx.x * blockDim.x + threadIdx.x;
    if (e < N_EDGES) {
        int s = ei[e], d = ei[N_EDGES + e];
        int pos = atomicAdd(&g_cursor[d], 1);
        g_csr[pos] = s;
    }
}

// ---------------- GEMM1 (bf16 MMA + ldmatrix, BM=64 for 3 CTAs/SM) ----------------
#define BM 64
#define BK 32
#define APITCH 40    // bf16 per A row (80 B)
#define BPITCH 136   // bf16 per B row (272 B)
__global__ void __launch_bounds__(256, 3)
k_gemm1(const float* __restrict__ X) {
    __shared__ __align__(16) __nv_bfloat16 Asm[2][BM][APITCH];  // 10 KB
    __shared__ __align__(16) __nv_bfloat16 Bsm[2][BK][BPITCH];  // 17 KB

    const int tid    = threadIdx.x;
    const int lane   = tid & 31;
    const int wid    = tid >> 5;
    const int warp_m = wid >> 2;              // 0..1 (32 rows)
    const int warp_n = wid & 3;               // 0..3 (32 cols)
    const int block_row = blockIdx.x * BM;
    const int grp = lane >> 2;
    const int qid = lane & 3;

    // staging slots: A row = 32 floats; 4 threads/row, 8 floats each
    const int a_r  = tid >> 2;                // 0..63
    const int a_k0 = (tid & 3) * 8;           // 0,8,16,24
    const int b_r  = tid >> 3;                // 0..31
    const int b_c  = tid & 7;                 // uint4 chunks b_c, b_c+8

    // ldmatrix lane offsets
    const int a_ro = (lane & 7) + ((lane >> 3) & 1) * 8;
    const int a_ko = (lane >> 4) * 8;
    const int b_ko = ((lane >> 3) & 1) * 8 + (lane & 7);
    const int b_no = (lane >> 4) * 8;

    const int  arow    = block_row + a_r;
    const bool arow_ok = arow < N_NODES;

    float acc[2][4][4];
    #pragma unroll
    for (int i = 0; i < 2; i++)
        #pragma unroll
        for (int j = 0; j < 4; j++)
            #pragma unroll
            for (int q = 0; q < 4; q++) acc[i][j][q] = 0.0f;

    float4 ar[2];
    uint4  br[2];
    const float4 z4 = make_float4(0.f, 0.f, 0.f, 0.f);
    const uint4* W1b4 = (const uint4*)g_w1bf;     // row k = 16 uint4

    auto ldg_tile = [&](int it) {
        int k0 = it * BK;
        const float* ap = X + (size_t)(arow_ok ? arow : 0) * NF + k0 + a_k0;
        ar[0] = arow_ok ? __ldg((const float4*)(ap))     : z4;
        ar[1] = arow_ok ? __ldg((const float4*)(ap + 4)) : z4;
        const uint4* bp = W1b4 + (size_t)(k0 + b_r) * 16;
        br[0] = __ldg(bp + b_c);
        br[1] = __ldg(bp + b_c + 8);
    };
    auto sts_tile = [&](int buf) {
        uint4 w;
        w.x = pack_bf16x2(ar[0].x, ar[0].y); w.y = pack_bf16x2(ar[0].z, ar[0].w);
        w.z = pack_bf16x2(ar[1].x, ar[1].y); w.w = pack_bf16x2(ar[1].z, ar[1].w);
        *(uint4*)&Asm[buf][a_r][a_k0] = w;
        *(uint4*)&Bsm[buf][b_r][b_c * 8]      = br[0];
        *(uint4*)&Bsm[buf][b_r][b_c * 8 + 64] = br[1];
    };

    const int NT = NF / BK;                   // 16
    ldg_tile(0);
    sts_tile(0);
    ldg_tile(1);
    __syncthreads();

    #pragma unroll 1
    for (int it = 0; it < NT; it++) {
        int cur = it & 1;
        #pragma unroll
        for (int ks = 0; ks < 2; ks++) {
            unsigned int af[2][4];
            #pragma unroll
            for (int mt = 0; mt < 2; mt++) {
                unsigned int addr = smem_u32(
                    &Asm[cur][warp_m * 32 + mt * 16 + a_ro][ks * 16 + a_ko]);
                ldsm_x4(af[mt][0], af[mt][1], af[mt][2], af[mt][3], addr);
            }
            unsigned int bfr[4][2];
            #pragma unroll
            for (int p = 0; p < 2; p++) {
                unsigned int r0, r1, r2, r3;
                unsigned int addr = smem_u32(
                    &Bsm[cur][ks * 16 + b_ko][warp_n * 32 + p * 16 + b_no]);
                ldsm_x4_t(r0, r1, r2, r3, addr);
                bfr[p * 2][0] = r0; bfr[p * 2][1] = r1;
                bfr[p * 2 + 1][0] = r2; bfr[p * 2 + 1][1] = r3;
            }
            #pragma unroll
            for (int mt = 0; mt < 2; mt++)
                #pragma unroll
                for (int nt = 0; nt < 4; nt++)
                    mma_bf16(acc[mt][nt], af[mt][0], af[mt][1], af[mt][2], af[mt][3],
                             bfr[nt][0], bfr[nt][1]);
        }
        if (it + 1 < NT) {
            sts_tile(1 - cur);
            if (it + 2 < NT) ldg_tile(it + 2);
        }
        __syncthreads();
    }

    // epilogue: scale by dinv, pack bf16x2, write hs1b
    #pragma unroll
    for (int mt = 0; mt < 2; mt++) {
        int r1 = block_row + warp_m * 32 + mt * 16 + grp;
        int r2 = r1 + 8;
        float dv1 = (r1 < N_NODES) ? g_dinv[r1] : 0.0f;
        float dv2 = (r2 < N_NODES) ? g_dinv[r2] : 0.0f;
        #pragma unroll
        for (int nt = 0; nt < 4; nt++) {
            int col = warp_n * 32 + nt * 8 + qid * 2;
            if (r1 < N_NODES)
                g_hs1b[(size_t)r1 * NHW + (col >> 1)] =
                    pack_bf16x2(acc[mt][nt][0] * dv1, acc[mt][nt][1] * dv1);
            if (r2 < N_NODES)
                g_hs1b[(size_t)r2 * NHW + (col >> 1)] =
                    pack_bf16x2(acc[mt][nt][2] * dv2, acc[mt][nt][3] * dv2);
        }
    }
}

// ---- layer1: gather bf16 hs1 -> z (smem, bf16), then block MMA z@W2 -> hs2b ----
#define Z_STRW 68
__global__ void __launch_bounds__(256)
k_layer1(const float* __restrict__ b1, const float* __restrict__ W2) {
    __shared__ unsigned int zsb[32][Z_STRW];
    __shared__ unsigned int W2T[NC][Z_STRW];
    __shared__ float b1s[NH];
    __shared__ float dvs[32];

    const int tid  = threadIdx.x;
    const int warp = tid >> 5;
    const int lane = tid & 31;
    const int grp  = lane >> 2;
    const int qid  = lane & 3;

    #pragma unroll
    for (int i = tid; i < NC * 64; i += 256) {
        int n = i >> 6, w = i & 63;
        W2T[n][w] = pack_bf16x2(W2[(2 * w) * NC + n], W2[(2 * w + 1) * NC + n]);
    }
    if (tid < NH) b1s[tid] = b1[tid];
    __syncthreads();

    #pragma unroll 1
    for (int it = 0; it < 4; it++) {
        int nl = it * 8 + warp;
        int n  = blockIdx.x * 32 + nl;
        float dv = g_dinv[n];
        if (lane == 0) dvs[nl] = dv;

        uint2 sw = *(const uint2*)(g_hs1b + (size_t)n * NHW + lane * 2);
        float a0 = bf_lo(sw.x), a1 = bf_hi(sw.x), a2 = bf_lo(sw.y), a3 = bf_hi(sw.y);

        int beg = g_rowptr[n], end = g_rowptr[n + 1];
        #pragma unroll 1
        for (int base = beg; base < end; base += 32) {
            int cnt = end - base; if (cnt > 32) cnt = 32;
            int idx = (base + lane < end) ? g_csr[base + lane] : 0;
            int j = 0;
            #pragma unroll 1
            for (; j + 4 <= cnt; j += 4) {
                int s0 = __shfl_sync(0xffffffffu, idx, j);
                int s1 = __shfl_sync(0xffffffffu, idx, j + 1);
                int s2 = __shfl_sync(0xffffffffu, idx, j + 2);
                int s3 = __shfl_sync(0xffffffffu, idx, j + 3);
                uint2 w0 = *(const uint2*)(g_hs1b + (size_t)s0 * NHW + lane * 2);
                uint2 w1 = *(const uint2*)(g_hs1b + (size_t)s1 * NHW + lane * 2);
                uint2 w2 = *(const uint2*)(g_hs1b + (size_t)s2 * NHW + lane * 2);
                uint2 w3 = *(const uint2*)(g_hs1b + (size_t)s3 * NHW + lane * 2);
                a0 += bf_lo(w0.x) + bf_lo(w1.x) + bf_lo(w2.x) + bf_lo(w3.x);
                a1 += bf_hi(w0.x) + bf_hi(w1.x) + bf_hi(w2.x) + bf_hi(w3.x);
                a2 += bf_lo(w0.y) + bf_lo(w1.y) + bf_lo(w2.y) + bf_lo(w3.y);
                a3 += bf_hi(w0.y) + bf_hi(w1.y) + bf_hi(w2.y) + bf_hi(w3.y);
            }
            #pragma unroll 1
            for (; j < cnt; j++) {
                int s = __shfl_sync(0xffffffffu, idx, j);
                uint2 w = *(const uint2*)(g_hs1b + (size_t)s * NHW + lane * 2);
                a0 += bf_lo(w.x); a1 += bf_hi(w.x); a2 += bf_lo(w.y); a3 += bf_hi(w.y);
            }
        }
        float z0 = fmaxf(dv * a0 + b1s[lane * 4 + 0], 0.0f);
        float z1 = fmaxf(dv * a1 + b1s[lane * 4 + 1], 0.0f);
        float z2 = fmaxf(dv * a2 + b1s[lane * 4 + 2], 0.0f);
        float z3 = fmaxf(dv * a3 + b1s[lane * 4 + 3], 0.0f);
        zsb[nl][lane * 2 + 0] = pack_bf16x2(z0, z1);
        zsb[nl][lane * 2 + 1] = pack_bf16x2(z2, z3);
    }
    __syncthreads();

    #pragma unroll 1
    for (int t = warp; t < 10; t += 8) {
        int mt = t / 5, nt = t % 5;
        float c[4] = {0.f, 0.f, 0.f, 0.f};
        #pragma unroll
        for (int ks = 0; ks < 8; ks++) {
            unsigned int a0 = zsb[mt * 16 + grp    ][ks * 8 + qid    ];
            unsigned int a1 = zsb[mt * 16 + grp + 8][ks * 8 + qid    ];
            unsigned int a2 = zsb[mt * 16 + grp    ][ks * 8 + qid + 4];
            unsigned int a3 = zsb[mt * 16 + grp + 8][ks * 8 + qid + 4];
            unsigned int b0 = W2T[nt * 8 + grp][ks * 8 + qid    ];
            unsigned int b1w = W2T[nt * 8 + grp][ks * 8 + qid + 4];
            mma_bf16(c, a0, a1, a2, a3, b0, b1w);
        }
        int n0 = blockIdx.x * 32 + mt * 16 + grp;
        int n1 = n0 + 8;
        float dv0 = dvs[mt * 16 + grp];
        float dv1 = dvs[mt * 16 + grp + 8];
        g_hs2b[(size_t)n0 * NCW + nt * 4 + qid] = pack_bf16x2(c[0] * dv0, c[1] * dv0);
        g_hs2b[(size_t)n1 * NCW + nt * 4 + qid] = pack_bf16x2(c[2] * dv1, c[3] * dv1);
    }
}

// ---- layer2: gather bf16 hs2 (self+neighbors), bias + log_softmax -> out ----
__global__ void __launch_bounds__(256)
k_layer2(const float* __restrict__ b2, float* __restrict__ out) {
    int n    = blockIdx.x * 8 + (threadIdx.x >> 5);
    int lane = threadIdx.x & 31;
    float dv = g_dinv[n];
    const bool act = lane < NCW;
    size_t baseb = (size_t)n * NCW;

    float v0 = 0.0f, v1 = 0.0f;
    if (act) {
        unsigned int w = g_hs2b[baseb + lane];
        v0 = bf_lo(w); v1 = bf_hi(w);
    }
    int beg = g_rowptr[n], end = g_rowptr[n + 1];
    #pragma unroll 1
    for (int base = beg; base < end; base += 32) {
        int cnt = end - base; if (cnt > 32) cnt = 32;
        int idx = (base + lane < end) ? g_csr[base + lane] : 0;
        int j = 0;
        #pragma unroll 1
        for (; j + 2 <= cnt; j += 2) {
            int s0 = __shfl_sync(0xffffffffu, idx, j);
            int s1 = __shfl_sync(0xffffffffu, idx, j + 1);
            if (act) {
                unsigned int w0 = g_hs2b[(size_t)s0 * NCW + lane];
                unsigned int w1 = g_hs2b[(size_t)s1 * NCW + lane];
                v0 += bf_lo(w0) + bf_lo(w1);
                v1 += bf_hi(w0) + bf_hi(w1);
            }
        }
        if (j < cnt) {
            int s = __shfl_sync(0xffffffffu, idx, j);
            if (act) {
                unsigned int w = g_hs2b[(size_t)s * NCW + lane];
                v0 += bf_lo(w); v1 += bf_hi(w);
            }
        }
    }

    if (act) {
        v0 = dv * v0 + b2[lane * 2];
        v1 = dv * v1 + b2[lane * 2 + 1];
    } else {
        v0 = -3.0e38f; v1 = -3.0e38f;
    }

    float m = fmaxf(v0, v1);
    #pragma unroll
    for (int off = 16; off; off >>= 1)
        m = fmaxf(m, __shfl_xor_sync(0xffffffffu, m, off));

    float ssum = act ? (expf(v0 - m) + expf(v1 - m)) : 0.0f;
    #pragma unroll
    for (int off = 16; off; off >>= 1)
        ssum += __shfl_xor_sync(0xffffffffu, ssum, off);

    float lse = m + logf(ssum);
    if (act)
        *(float2*)(out + (size_t)n * NC + lane * 2) = make_float2(v0 - lse, v1 - lse);
}

// ---------------- launch ----------------
extern "C" void kernel_launch(void* const* d_in, const int* in_sizes, int n_in,
                              void* d_out, int out_size) {
    const float* x = 0; const int* ei = 0;
    const float* W1 = 0; const float* b1 = 0;
    const float* W2 = 0; const float* b2 = 0;
    for (int i = 0; i < n_in; i++) {
        switch (in_sizes[i]) {
            case 51200000: x  = (const float*)d_in[i]; break;
            case 3200000:  ei = (const int*)d_in[i];   break;
            case 65536:    W1 = (const float*)d_in[i]; break;
            case 128:      b1 = (const float*)d_in[i]; break;
            case 5120:     W2 = (const float*)d_in[i]; break;
            case 40:       b2 = (const float*)d_in[i]; break;
        }
    }
    float* out = (float*)d_out;

    k_prep<<<(N_NODES + 255) / 256, 256>>>(W1);          // zero cnt + pack W1 bf16
    k_deg<<<(N_EDGES + 255) / 256, 256>>>(ei);
    k_scan1<<<SCAN_NB, SCAN_CH>>>();                     // scan phase1 + dinv
    k_gemm1<<<(N_NODES + BM - 1) / BM, 256>>>(x);        // 4th = profiled
    k_scan2<<<1, 1024>>>();
    k_scan3<<<SCAN_NB, SCAN_CH>>>();
    k_fill<<<(N_EDGES + 255) / 256, 256>>>(ei);

    k_layer1<<<N_NODES / 32, 256>>>(b1, W2);
    k_layer2<<<N_NODES / 8, 256>>>(b2, out);
}